// round 8
// baseline (speedup 1.0000x reference)
#include <cuda_runtime.h>
#include <cuda_fp16.h>
#include <math.h>

constexpr int BB = 8;
constexpr int TT = 128;
constexpr int NN = 256;
constexpr int FF = 128;
constexpr int MTOT = BB * TT * NN;   // 262144
constexpr int HP = 136;              // smem half pitch (padded)

// -------- scratch (device globals) --------
__device__ __half g_attn[MTOT * FF];
__device__ __align__(16) __half g_wq16 [FF * FF];
__device__ __align__(16) __half g_wkh16[FF * FF];
__device__ __align__(16) __half g_wvh16[FF * FF];
__device__ __align__(16) __half g_wo16 [FF * FF];
__device__ __align__(16) __half g_wf116[FF * FF];
__device__ __align__(16) __half g_wf216[FF * FF];

// ------------------- mma.sync helpers -------------------
__device__ __forceinline__ void ldsm4(unsigned& r0, unsigned& r1, unsigned& r2, unsigned& r3, unsigned addr) {
    asm volatile("ldmatrix.sync.aligned.m8n8.x4.shared.b16 {%0,%1,%2,%3},[%4];"
                 : "=r"(r0), "=r"(r1), "=r"(r2), "=r"(r3) : "r"(addr));
}
__device__ __forceinline__ void ldsm4t(unsigned& r0, unsigned& r1, unsigned& r2, unsigned& r3, unsigned addr) {
    asm volatile("ldmatrix.sync.aligned.m8n8.x4.trans.shared.b16 {%0,%1,%2,%3},[%4];"
                 : "=r"(r0), "=r"(r1), "=r"(r2), "=r"(r3) : "r"(addr));
}
__device__ __forceinline__ void mma16816(float* cc, const unsigned* aa, const unsigned* bb) {
    asm volatile("mma.sync.aligned.m16n8k16.row.col.f32.f16.f16.f32 "
                 "{%0,%1,%2,%3},{%4,%5,%6,%7},{%8,%9},{%0,%1,%2,%3};"
                 : "+f"(cc[0]), "+f"(cc[1]), "+f"(cc[2]), "+f"(cc[3])
                 : "r"(aa[0]), "r"(aa[1]), "r"(aa[2]), "r"(aa[3]), "r"(bb[0]), "r"(bb[1]));
}
__device__ __forceinline__ unsigned sptr(const void* ptr) {
    return (unsigned)__cvta_generic_to_shared(ptr);
}
__device__ __forceinline__ unsigned pack2(float a, float b) {
    __half2 h = __floats2half2_rn(a, b);
    return *reinterpret_cast<unsigned*>(&h);
}

// ---------- 256-thread (8-warp) tile GEMM: warp computes 64x32 ----------
__device__ __forceinline__ void mma_tile(const __half* Amat, const __half* Bmat, float acc[4][4][4]) {
    const int lane = threadIdx.x & 31;
    const int warp = threadIdx.x >> 5;
    const int wy = warp >> 2;
    const int wx = warp & 3;
    const int r16 = lane & 15;
    const int hi8 = (lane >> 4) * 8;
    #pragma unroll
    for (int k0 = 0; k0 < 128; k0 += 16) {
        unsigned afrag[4][4];
        #pragma unroll
        for (int i = 0; i < 4; ++i) {
            unsigned addr = sptr(Amat + (wy * 64 + i * 16 + r16) * HP + k0 + hi8);
            ldsm4(afrag[i][0], afrag[i][1], afrag[i][2], afrag[i][3], addr);
        }
        unsigned bfrag[4][2];
        #pragma unroll
        for (int jj = 0; jj < 2; ++jj) {
            unsigned addr = sptr(Bmat + (k0 + r16) * HP + wx * 32 + jj * 16 + hi8);
            unsigned t0, t1, t2, t3;
            ldsm4t(t0, t1, t2, t3, addr);
            bfrag[jj * 2 + 0][0] = t0; bfrag[jj * 2 + 0][1] = t1;
            bfrag[jj * 2 + 1][0] = t2; bfrag[jj * 2 + 1][1] = t3;
        }
        #pragma unroll
        for (int i = 0; i < 4; ++i)
            #pragma unroll
            for (int j = 0; j < 4; ++j)
                mma16816(acc[i][j], afrag[i], bfrag[j]);
    }
}

// ---------- 512-thread (16-warp) tile GEMM: warp computes 32x32 ----------
__device__ __forceinline__ void mma_tile512(const __half* Amat, const __half* Bmat, float acc[2][4][4]) {
    const int lane = threadIdx.x & 31;
    const int warp = threadIdx.x >> 5;
    const int wy = warp >> 2;        // 0..3
    const int wx = warp & 3;         // 0..3
    const int r16 = lane & 15;
    const int hi8 = (lane >> 4) * 8;
    #pragma unroll
    for (int k0 = 0; k0 < 128; k0 += 16) {
        unsigned afrag[2][4];
        #pragma unroll
        for (int i = 0; i < 2; ++i) {
            unsigned addr = sptr(Amat + (wy * 32 + i * 16 + r16) * HP + k0 + hi8);
            ldsm4(afrag[i][0], afrag[i][1], afrag[i][2], afrag[i][3], addr);
        }
        unsigned bfrag[4][2];
        #pragma unroll
        for (int jj = 0; jj < 2; ++jj) {
            unsigned addr = sptr(Bmat + (k0 + r16) * HP + wx * 32 + jj * 16 + hi8);
            unsigned t0, t1, t2, t3;
            ldsm4t(t0, t1, t2, t3, addr);
            bfrag[jj * 2 + 0][0] = t0; bfrag[jj * 2 + 0][1] = t1;
            bfrag[jj * 2 + 1][0] = t2; bfrag[jj * 2 + 1][1] = t3;
        }
        #pragma unroll
        for (int i = 0; i < 2; ++i)
            #pragma unroll
            for (int j = 0; j < 4; ++j)
                mma16816(acc[i][j], afrag[i], bfrag[j]);
    }
}

__device__ __forceinline__ void store_tile512(__half* dst, float acc[2][4][4],
                                              const float* __restrict__ bias, bool doRelu) {
    const int lane = threadIdx.x & 31;
    const int warp = threadIdx.x >> 5;
    const int wy = warp >> 2;
    const int wx = warp & 3;
    const int gid = lane >> 2;
    const int tig = lane & 3;
    #pragma unroll
    for (int i = 0; i < 2; ++i) {
        int row = wy * 32 + i * 16 + gid;
        #pragma unroll
        for (int j = 0; j < 4; ++j) {
            int col = wx * 32 + j * 8 + tig * 2;
            float2 bv = *(const float2*)(bias + col);
            float o0 = acc[i][j][0] + bv.x;
            float o1 = acc[i][j][1] + bv.y;
            float o2 = acc[i][j][2] + bv.x;
            float o3 = acc[i][j][3] + bv.y;
            if (doRelu) {
                o0 = fmaxf(o0, 0.f); o1 = fmaxf(o1, 0.f);
                o2 = fmaxf(o2, 0.f); o3 = fmaxf(o3, 0.f);
            }
            *(__half2*)(dst + row * HP + col)       = __floats2half2_rn(o0, o1);
            *(__half2*)(dst + (row + 8) * HP + col) = __floats2half2_rn(o2, o3);
        }
    }
}

// store for 256-thread tail kernel (8-warp, 64x32 per warp)
__device__ __forceinline__ void store_tile(__half* dst, float acc[4][4][4],
                                           const float* __restrict__ bias, bool doRelu) {
    const int lane = threadIdx.x & 31;
    const int warp = threadIdx.x >> 5;
    const int wy = warp >> 2;
    const int wx = warp & 3;
    const int gid = lane >> 2;
    const int tig = lane & 3;
    #pragma unroll
    for (int i = 0; i < 4; ++i) {
        int row = wy * 64 + i * 16 + gid;
        #pragma unroll
        for (int j = 0; j < 4; ++j) {
            int col = wx * 32 + j * 8 + tig * 2;
            float2 bv = *(const float2*)(bias + col);
            float o0 = acc[i][j][0] + bv.x;
            float o1 = acc[i][j][1] + bv.y;
            float o2 = acc[i][j][2] + bv.x;
            float o3 = acc[i][j][3] + bv.y;
            if (doRelu) {
                o0 = fmaxf(o0, 0.f); o1 = fmaxf(o1, 0.f);
                o2 = fmaxf(o2, 0.f); o3 = fmaxf(o3, 0.f);
            }
            *(__half2*)(dst + row * HP + col)       = __floats2half2_rn(o0, o1);
            *(__half2*)(dst + (row + 8) * HP + col) = __floats2half2_rn(o2, o3);
        }
    }
}

// =====================================================================
// Kernel 0: one-time fp32 -> fp16 weight conversion.
// =====================================================================
__global__ void conv_kernel(const float* __restrict__ Wq, const float* __restrict__ Wkh,
                            const float* __restrict__ Wvh, const float* __restrict__ Wo,
                            const float* __restrict__ Wf1, const float* __restrict__ Wf2)
{
    int i = blockIdx.x * 256 + threadIdx.x;
    g_wq16[i]  = __float2half(Wq[i]);
    g_wkh16[i] = __float2half(Wkh[i]);
    g_wvh16[i] = __float2half(Wvh[i]);
    g_wo16[i]  = __float2half(Wo[i]);
    g_wf116[i] = __float2half(Wf1[i]);
    g_wf216[i] = __float2half(Wf2[i]);
}

// =====================================================================
// Split attention: warp (G,H): rows [16G,16G+16), s-tiles js in
// [H*(G+1), H*(G+1)+G] (G+1 tiles of 8 each half). Split-softmax:
// exchange per-row (m,l) via smem; H1 writes alpha-scaled partial O
// (f16) to B1; H0 combines, normalizes, stores to g_attn.
// Each instantiation executes exactly TWO __syncthreads().
// =====================================================================
template<int G, int H>
__device__ __forceinline__ void attn_half(const __half* Qs, const __half* Ks, const __half* Vs,
                                          __half* B1, float* pm, float* pl,
                                          int base, int lane)
{
    constexpr int NT = G + 1;             // s-tiles this half owns
    constexpr int JS0 = (H == 0) ? 0 : (G + 1);
    constexpr int NPAIR = (NT + 1) / 2;
    const int r16 = lane & 15;
    const int hi8 = (lane >> 4) * 8;
    const int gid = lane >> 2;
    const int tig = lane & 3;
    const int tlo = 16 * G + gid;
    const int thi = tlo + 8;

    // ---- S = Q K^T over this half's s-range ----
    float c[NT][4];
    #pragma unroll
    for (int jt = 0; jt < NT; ++jt) { c[jt][0] = 0.f; c[jt][1] = 0.f; c[jt][2] = 0.f; c[jt][3] = 0.f; }

    #pragma unroll
    for (int k = 0; k < 8; ++k) {
        unsigned aq[4];
        ldsm4(aq[0], aq[1], aq[2], aq[3], sptr(Qs + (16 * G + r16) * HP + k * 16 + hi8));
        #pragma unroll
        for (int jp = 0; jp < NPAIR; ++jp) {
            unsigned t0, t1, t2, t3;
            ldsm4(t0, t1, t2, t3, sptr(Ks + (8 * JS0 + 16 * jp + r16) * HP + k * 16 + hi8));
            unsigned bE[2] = { t0, t2 };
            mma16816(c[2 * jp], aq, bE);
            if (2 * jp + 1 < NT) {
                unsigned bO[2] = { t1, t3 };
                mma16816(c[2 * jp + 1], aq, bO);
            }
        }
    }

    // ---- mask + scale + local max ----
    const float scale = 0.08838834764831845f;   // 1/sqrt(128)
    float mlo = -1e30f, mhi = -1e30f;
    #pragma unroll
    for (int jt = 0; jt < NT; ++jt) {
        int s0 = 8 * (JS0 + jt) + 2 * tig;
        int s1 = s0 + 1;
        float v0 = c[jt][0] * scale;
        float v1 = c[jt][1] * scale;
        float v2 = c[jt][2] * scale;
        float v3 = c[jt][3] * scale;
        if (s0 > tlo) v0 = -1e30f;
        if (s1 > tlo) v1 = -1e30f;
        if (s0 > thi) v2 = -1e30f;
        if (s1 > thi) v3 = -1e30f;
        c[jt][0] = v0; c[jt][1] = v1; c[jt][2] = v2; c[jt][3] = v3;
        mlo = fmaxf(mlo, fmaxf(v0, v1));
        mhi = fmaxf(mhi, fmaxf(v2, v3));
    }
    #pragma unroll
    for (int o = 1; o <= 2; o <<= 1) {
        mlo = fmaxf(mlo, __shfl_xor_sync(0xffffffffu, mlo, o));
        mhi = fmaxf(mhi, __shfl_xor_sync(0xffffffffu, mhi, o));
    }

    // ---- local exp + local sum ----
    float slo = 0.f, shi = 0.f;
    #pragma unroll
    for (int jt = 0; jt < NT; ++jt) {
        c[jt][0] = __expf(c[jt][0] - mlo);
        c[jt][1] = __expf(c[jt][1] - mlo);
        c[jt][2] = __expf(c[jt][2] - mhi);
        c[jt][3] = __expf(c[jt][3] - mhi);
        slo += c[jt][0] + c[jt][1];
        shi += c[jt][2] + c[jt][3];
    }
    #pragma unroll
    for (int o = 1; o <= 2; o <<= 1) {
        slo += __shfl_xor_sync(0xffffffffu, slo, o);
        shi += __shfl_xor_sync(0xffffffffu, shi, o);
    }
    if (tig == 0) {
        pm[H * 128 + tlo] = mlo;  pl[H * 128 + tlo] = slo;
        pm[H * 128 + thi] = mhi;  pl[H * 128 + thi] = shi;
    }
    __syncthreads();   // (1) exchange m/l across halves

    // ---- global m, l, correction factors ----
    float m0lo = pm[tlo], m1lo = pm[128 + tlo];
    float m0hi = pm[thi], m1hi = pm[128 + thi];
    float mglo = fmaxf(m0lo, m1lo);
    float mghi = fmaxf(m0hi, m1hi);
    float lglo = pl[tlo] * __expf(m0lo - mglo) + pl[128 + tlo] * __expf(m1lo - mglo);
    float lghi = pl[thi] * __expf(m0hi - mghi) + pl[128 + thi] * __expf(m1hi - mghi);
    float alo = __expf((H == 0 ? m0lo : m1lo) - mglo);
    float ahi = __expf((H == 0 ? m0hi : m1hi) - mghi);
    float invlo = 1.f / lglo;
    float invhi = 1.f / lghi;

    // ---- partial O = P V over this half's s-range ----
    float ov[16][4];
    #pragma unroll
    for (int jt = 0; jt < 16; ++jt) { ov[jt][0] = 0.f; ov[jt][1] = 0.f; ov[jt][2] = 0.f; ov[jt][3] = 0.f; }

    #pragma unroll
    for (int kp = 0; kp < NPAIR; ++kp) {
        unsigned ap[4];
        ap[0] = pack2(c[2 * kp][0], c[2 * kp][1]);
        ap[1] = pack2(c[2 * kp][2], c[2 * kp][3]);
        if (2 * kp + 1 < NT) {
            ap[2] = pack2(c[2 * kp + 1][0], c[2 * kp + 1][1]);
            ap[3] = pack2(c[2 * kp + 1][2], c[2 * kp + 1][3]);
        } else {
            ap[2] = 0u; ap[3] = 0u;
        }
        #pragma unroll
        for (int jfp = 0; jfp < 8; ++jfp) {
            unsigned t0, t1, t2, t3;
            ldsm4t(t0, t1, t2, t3, sptr(Vs + (8 * JS0 + 16 * kp + r16) * HP + jfp * 16 + hi8));
            unsigned b0[2] = { t0, t1 };
            unsigned b1[2] = { t2, t3 };
            mma16816(ov[2 * jfp],     ap, b0);
            mma16816(ov[2 * jfp + 1], ap, b1);
        }
    }

    // ---- H1 publishes alpha-scaled partial (f16) ----
    if (H == 1) {
        #pragma unroll
        for (int jt = 0; jt < 16; ++jt) {
            int col = jt * 8 + tig * 2;
            *(__half2*)(B1 + tlo * HP + col) = __floats2half2_rn(ov[jt][0] * alo, ov[jt][1] * alo);
            *(__half2*)(B1 + thi * HP + col) = __floats2half2_rn(ov[jt][2] * ahi, ov[jt][3] * ahi);
        }
    }
    __syncthreads();   // (2) partial O visible

    // ---- H0 combines + normalizes + stores ----
    if (H == 0) {
        __half* olo = g_attn + (base + tlo * NN) * FF;
        __half* ohi = g_attn + (base + thi * NN) * FF;
        #pragma unroll
        for (int jt = 0; jt < 16; ++jt) {
            int col = jt * 8 + tig * 2;
            float2 p0 = __half22float2(*(const __half2*)(B1 + tlo * HP + col));
            float2 p1 = __half22float2(*(const __half2*)(B1 + thi * HP + col));
            float o0 = (ov[jt][0] * alo + p0.x) * invlo;
            float o1 = (ov[jt][1] * alo + p0.y) * invlo;
            float o2 = (ov[jt][2] * ahi + p1.x) * invhi;
            float o3 = (ov[jt][3] * ahi + p1.y) * invhi;
            *(__half2*)(olo + col) = __floats2half2_rn(o0, o1);
            *(__half2*)(ohi + col) = __floats2half2_rn(o2, o3);
        }
    }
}

// =====================================================================
// Kernel 1 (fused qkv + attention), one head per CTA, 512 threads.
// =====================================================================
__global__ __launch_bounds__(512, 1) void fused_attn_kernel(
    const float* __restrict__ xl, const float* __restrict__ xh,
    const float* __restrict__ te,
    const float* __restrict__ bq, const float* __restrict__ bkh,
    const float* __restrict__ bvh)
{
    extern __shared__ char smraw[];
    __half* X1 = (__half*)smraw;          // xh+te -> later Q
    __half* X2 = X1 + 128 * HP;           // xl+te -> later B1 (H1 partial O)
    __half* W0 = X2 + 128 * HP;           // Wkh -> Wq
    __half* W1 = W0 + 128 * HP;           // Wvh
    __half* Ks = W1 + 128 * HP;
    __half* Vs = Ks + 128 * HP;
    float* pm = (float*)(Vs + 128 * HP);  // [2][128]
    float* pl = pm + 256;                 // [2][128]

    const int head = blockIdx.x;
    const int bidx = head >> 8;
    const int nidx = head & 255;
    const int base = bidx * TT * NN + nidx;   // row(t)=base+t*NN

    const int tid = threadIdx.x;
    const int ww = tid >> 5;
    const int lane = tid & 31;

    const float4* xl4 = (const float4*)xl;
    const float4* xh4 = (const float4*)xh;
    const float4* te4 = (const float4*)te;

    // ---- stage X1, X2, W0=Wkh, W1=Wvh ----
    for (int v = tid; v < 4096; v += 512) {
        int row = v >> 5;
        int c4 = v & 31;
        float4 tval = te4[(bidx * TT + row) * 32 + c4];
        float4 ah = xh4[(base + row * NN) * 32 + c4];
        __half2* dh = (__half2*)(X1 + row * HP + c4 * 4);
        dh[0] = __floats2half2_rn(ah.x + tval.x, ah.y + tval.y);
        dh[1] = __floats2half2_rn(ah.z + tval.z, ah.w + tval.w);
        float4 al = xl4[(base + row * NN) * 32 + c4];
        __half2* dl = (__half2*)(X2 + row * HP + c4 * 4);
        dl[0] = __floats2half2_rn(al.x + tval.x, al.y + tval.y);
        dl[1] = __floats2half2_rn(al.z + tval.z, al.w + tval.w);
    }
    for (int v = tid; v < 2048; v += 512) {
        int row = v >> 4;
        int q16 = v & 15;
        ((uint4*)(W0 + row * HP))[q16] = ((const uint4*)g_wkh16)[row * 16 + q16];
        ((uint4*)(W1 + row * HP))[q16] = ((const uint4*)g_wvh16)[row * 16 + q16];
    }
    __syncthreads();

    // ---- K, V GEMMs ----
    {
        float accK[2][4][4] = {};
        mma_tile512(X1, W0, accK);
        float accV[2][4][4] = {};
        mma_tile512(X1, W1, accV);
        __syncthreads();                 // X1/W0/W1 reads done
        store_tile512(Ks, accK, bkh, true);
        store_tile512(Vs, accV, bvh, true);
    }
    for (int v = tid; v < 2048; v += 512) {
        int row = v >> 4;
        int q16 = v & 15;
        ((uint4*)(W0 + row * HP))[q16] = ((const uint4*)g_wq16)[row * 16 + q16];
    }
    __syncthreads();

    // ---- Q GEMM -> X1 ----
    {
        float accQ[2][4][4] = {};
        mma_tile512(X2, W0, accQ);
        store_tile512(X1, accQ, bq, false);   // X1 free since first sync
    }
    __syncthreads();                          // Q/K/V visible; X2 free -> B1

    // ---- split causal attention (each case: exactly 2 barriers inside) ----
    const int G = ww >> 1;
    const int H = ww & 1;
    switch (G * 2 + H) {
        case 0:  attn_half<0, 0>(X1, Ks, Vs, X2, pm, pl, base, lane); break;
        case 1:  attn_half<0, 1>(X1, Ks, Vs, X2, pm, pl, base, lane); break;
        case 2:  attn_half<1, 0>(X1, Ks, Vs, X2, pm, pl, base, lane); break;
        case 3:  attn_half<1, 1>(X1, Ks, Vs, X2, pm, pl, base, lane); break;
        case 4:  attn_half<2, 0>(X1, Ks, Vs, X2, pm, pl, base, lane); break;
        case 5:  attn_half<2, 1>(X1, Ks, Vs, X2, pm, pl, base, lane); break;
        case 6:  attn_half<3, 0>(X1, Ks, Vs, X2, pm, pl, base, lane); break;
        case 7:  attn_half<3, 1>(X1, Ks, Vs, X2, pm, pl, base, lane); break;
        case 8:  attn_half<4, 0>(X1, Ks, Vs, X2, pm, pl, base, lane); break;
        case 9:  attn_half<4, 1>(X1, Ks, Vs, X2, pm, pl, base, lane); break;
        case 10: attn_half<5, 0>(X1, Ks, Vs, X2, pm, pl, base, lane); break;
        case 11: attn_half<5, 1>(X1, Ks, Vs, X2, pm, pl, base, lane); break;
        case 12: attn_half<6, 0>(X1, Ks, Vs, X2, pm, pl, base, lane); break;
        case 13: attn_half<6, 1>(X1, Ks, Vs, X2, pm, pl, base, lane); break;
        case 14: attn_half<7, 0>(X1, Ks, Vs, X2, pm, pl, base, lane); break;
        default: attn_half<7, 1>(X1, Ks, Vs, X2, pm, pl, base, lane); break;
    }
}

// =====================================================================
// Kernel 2 (fused proj+ffn), 256 threads, 2 CTAs/SM. (unchanged)
// =====================================================================
__global__ __launch_bounds__(256, 2) void tail_kernel(
    float* __restrict__ outp,
    const float* __restrict__ xl, const float* __restrict__ te,
    const float* __restrict__ bo, const float* __restrict__ bf1,
    const float* __restrict__ bf2)
{
    extern __shared__ char smraw[];
    __half* A1 = (__half*)smraw;
    __half* A2 = A1 + 128 * HP;
    __half* Wb = A2 + 128 * HP;
    float* red1 = (float*)(Wb + 128 * HP);
    float* red2 = red1 + 512;

    const int m0 = blockIdx.x * 128;
    const int tid = threadIdx.x;
    const float* teRow = te + (m0 / NN) * FF;

    for (int v = tid; v < 2048; v += 256) {
        int row = v >> 4;
        int q16 = v & 15;
        ((uint4*)(A1 + row * HP))[q16] = ((const uint4*)(g_attn + (m0 + row) * FF))[q16];
        ((uint4*)(Wb + row * HP))[q16] = ((const uint4*)g_wo16)[row * 16 + q16];
    }
    __syncthreads();

    const int lane = tid & 31;
    const int warp = tid >> 5;
    const int wy = warp >> 2;
    const int wx = warp & 3;
    const int gid = lane >> 2;
    const int tig = lane & 3;

    float acc[4][4][4] = {};
    mma_tile(A1, Wb, acc);
    __syncthreads();

    #pragma unroll
    for (int i = 0; i < 4; ++i) {
        int rlo = wy * 64 + i * 16 + gid;
        int rhi = rlo + 8;
        float s1lo = 0.f, s2lo = 0.f, s1hi = 0.f, s2hi = 0.f;
        #pragma unroll
        for (int j = 0; j < 4; ++j) {
            int col = wx * 32 + j * 8 + tig * 2;
            float2 bv = *(const float2*)(bo + col);
            float2 x0 = *(const float2*)(xl + (m0 + rlo) * FF + col);
            float2 x1 = *(const float2*)(xl + (m0 + rhi) * FF + col);
            float2 t0 = *(const float2*)(teRow + col);
            float v0 = acc[i][j][0] + bv.x + x0.x + t0.x;
            float v1 = acc[i][j][1] + bv.y + x0.y + t0.y;
            float v2 = acc[i][j][2] + bv.x + x1.x + t0.x;
            float v3 = acc[i][j][3] + bv.y + x1.y + t0.y;
            acc[i][j][0] = v0; acc[i][j][1] = v1;
            acc[i][j][2] = v2; acc[i][j][3] = v3;
            s1lo += v0 + v1; s2lo += v0 * v0 + v1 * v1;
            s1hi += v2 + v3; s2hi += v2 * v2 + v3 * v3;
        }
        #pragma unroll
        for (int o = 1; o <= 2; o <<= 1) {
            s1lo += __shfl_xor_sync(0xffffffffu, s1lo, o);
            s2lo += __shfl_xor_sync(0xffffffffu, s2lo, o);
            s1hi += __shfl_xor_sync(0xffffffffu, s1hi, o);
            s2hi += __shfl_xor_sync(0xffffffffu, s2hi, o);
        }
        if (tig == 0) {
            red1[rlo * 4 + wx] = s1lo; red2[rlo * 4 + wx] = s2lo;
            red1[rhi * 4 + wx] = s1hi; red2[rhi * 4 + wx] = s2hi;
        }
    }
    __syncthreads();

    #pragma unroll
    for (int i = 0; i < 4; ++i) {
        int rlo = wy * 64 + i * 16 + gid;
        int rhi = rlo + 8;
        float mlo = (red1[rlo * 4] + red1[rlo * 4 + 1] + red1[rlo * 4 + 2] + red1[rlo * 4 + 3]) * 0.0078125f;
        float vlo = (red2[rlo * 4] + red2[rlo * 4 + 1] + red2[rlo * 4 + 2] + red2[rlo * 4 + 3]) * 0.0078125f - mlo * mlo;
        float rslo = rsqrtf(vlo + 1e-5f);
        float mhi = (red1[rhi * 4] + red1[rhi * 4 + 1] + red1[rhi * 4 + 2] + red1[rhi * 4 + 3]) * 0.0078125f;
        float vhi = (red2[rhi * 4] + red2[rhi * 4 + 1] + red2[rhi * 4 + 2] + red2[rhi * 4 + 3]) * 0.0078125f - mhi * mhi;
        float rshi = rsqrtf(vhi + 1e-5f);
        #pragma unroll
        for (int j = 0; j < 4; ++j) {
            int col = wx * 32 + j * 8 + tig * 2;
            *(__half2*)(A1 + rlo * HP + col) =
                __floats2half2_rn((acc[i][j][0] - mlo) * rslo, (acc[i][j][1] - mlo) * rslo);
            *(__half2*)(A1 + rhi * HP + col) =
                __floats2half2_rn((acc[i][j][2] - mhi) * rshi, (acc[i][j][3] - mhi) * rshi);
        }
    }
    for (int v = tid; v < 2048; v += 256) {
        int row = v >> 4;
        int q16 = v & 15;
        ((uint4*)(Wb + row * HP))[q16] = ((const uint4*)g_wf116)[row * 16 + q16];
    }
    __syncthreads();

    float acc2[4][4][4] = {};
    mma_tile(A1, Wb, acc2);
    __syncthreads();
    store_tile(A2, acc2, bf1, true);
    for (int v = tid; v < 2048; v += 256) {
        int row = v >> 4;
        int q16 = v & 15;
        ((uint4*)(Wb + row * HP))[q16] = ((const uint4*)g_wf216)[row * 16 + q16];
    }
    __syncthreads();

    float acc3[4][4][4] = {};
    mma_tile(A2, Wb, acc3);

    #pragma unroll
    for (int i = 0; i < 4; ++i) {
        int rlo = wy * 64 + i * 16 + gid;
        int rhi = rlo + 8;
        float s1lo = 0.f, s2lo = 0.f, s1hi = 0.f, s2hi = 0.f;
        #pragma unroll
        for (int j = 0; j < 4; ++j) {
            int col = wx * 32 + j * 8 + tig * 2;
            float2 bv = *(const float2*)(bf2 + col);
            float2 l0 = __half22float2(*(const __half2*)(A1 + rlo * HP + col));
            float2 l1 = __half22float2(*(const __half2*)(A1 + rhi * HP + col));
            float v0 = acc3[i][j][0] + bv.x + l0.x;
            float v1 = acc3[i][j][1] + bv.y + l0.y;
            float v2 = acc3[i][j][2] + bv.x + l1.x;
            float v3 = acc3[i][j][3] + bv.y + l1.y;
            acc3[i][j][0] = v0; acc3[i][j][1] = v1;
            acc3[i][j][2] = v2; acc3[i][j][3] = v3;
            s1lo += v0 + v1; s2lo += v0 * v0 + v1 * v1;
            s1hi += v2 + v3; s2hi += v2 * v2 + v3 * v3;
        }
        #pragma unroll
        for (int o = 1; o <= 2; o <<= 1) {
            s1lo += __shfl_xor_sync(0xffffffffu, s1lo, o);
            s2lo += __shfl_xor_sync(0xffffffffu, s2lo, o);
            s1hi += __shfl_xor_sync(0xffffffffu, s1hi, o);
            s2hi += __shfl_xor_sync(0xffffffffu, s2hi, o);
        }
        if (tig == 0) {
            red1[rlo * 4 + wx] = s1lo; red2[rlo * 4 + wx] = s2lo;
            red1[rhi * 4 + wx] = s1hi; red2[rhi * 4 + wx] = s2hi;
        }
    }
    __syncthreads();

    #pragma unroll
    for (int i = 0; i < 4; ++i) {
        int rlo = wy * 64 + i * 16 + gid;
        int rhi = rlo + 8;
        float mlo = (red1[rlo * 4] + red1[rlo * 4 + 1] + red1[rlo * 4 + 2] + red1[rlo * 4 + 3]) * 0.0078125f;
        float vlo = (red2[rlo * 4] + red2[rlo * 4 + 1] + red2[rlo * 4 + 2] + red2[rlo * 4 + 3]) * 0.0078125f - mlo * mlo;
        float rslo = rsqrtf(vlo + 1e-5f);
        float mhi = (red1[rhi * 4] + red1[rhi * 4 + 1] + red1[rhi * 4 + 2] + red1[rhi * 4 + 3]) * 0.0078125f;
        float vhi = (red2[rhi * 4] + red2[rhi * 4 + 1] + red2[rhi * 4 + 2] + red2[rhi * 4 + 3]) * 0.0078125f - mhi * mhi;
        float rshi = rsqrtf(vhi + 1e-5f);
        #pragma unroll
        for (int j = 0; j < 4; ++j) {
            int col = wx * 32 + j * 8 + tig * 2;
            float2 o0, o1;
            o0.x = (acc3[i][j][0] - mlo) * rslo;
            o0.y = (acc3[i][j][1] - mlo) * rslo;
            o1.x = (acc3[i][j][2] - mhi) * rshi;
            o1.y = (acc3[i][j][3] - mhi) * rshi;
            *(float2*)(outp + (m0 + rlo) * FF + col) = o0;
            *(float2*)(outp + (m0 + rhi) * FF + col) = o1;
        }
    }
}

// =====================================================================
extern "C" void kernel_launch(void* const* d_in, const int* in_sizes, int n_in,
                              void* d_out, int out_size)
{
    const float* xl  = (const float*)d_in[0];
    const float* xh  = (const float*)d_in[1];
    const float* te  = (const float*)d_in[2];
    const float* Wq  = (const float*)d_in[3];
    const float* bq  = (const float*)d_in[4];
    const float* Wkh = (const float*)d_in[5];
    const float* bkh = (const float*)d_in[6];
    const float* Wvh = (const float*)d_in[7];
    const float* bvh = (const float*)d_in[8];
    const float* Wo  = (const float*)d_in[9];
    const float* bo  = (const float*)d_in[10];
    const float* Wf1 = (const float*)d_in[11];
    const float* bf1 = (const float*)d_in[12];
    const float* Wf2 = (const float*)d_in[13];
    const float* bf2 = (const float*)d_in[14];
    float* outp = (float*)d_out;

    const int smFused = 6 * 128 * HP * 2 + 2 * 1024;          // 210944
    const int smTail  = 3 * 128 * HP * 2 + 2 * 4096;          // 112640

    cudaFuncSetAttribute(fused_attn_kernel, cudaFuncAttributeMaxDynamicSharedMemorySize, smFused);
    cudaFuncSetAttribute(tail_kernel,       cudaFuncAttributeMaxDynamicSharedMemorySize, smTail);

    conv_kernel<<<64, 256>>>(Wq, Wkh, Wvh, Wo, Wf1, Wf2);
    fused_attn_kernel<<<BB * NN, 512, smFused>>>(xl, xh, te, bq, bkh, bvh);
    tail_kernel<<<MTOT / 128, 256, smTail>>>(outp, xl, te, bo, bf1, bf2);
}

// round 9
// speedup vs baseline: 1.0914x; 1.0914x over previous
#include <cuda_runtime.h>
#include <cuda_fp16.h>
#include <math.h>

constexpr int BB = 8;
constexpr int TT = 128;
constexpr int NN = 256;
constexpr int FF = 128;
constexpr int MTOT = BB * TT * NN;   // 262144
constexpr int HP = 136;              // smem half pitch (padded)

// -------- scratch (device globals) --------
__device__ __half g_attn[MTOT * FF];
__device__ __align__(16) __half g_wq16 [FF * FF];
__device__ __align__(16) __half g_wkh16[FF * FF];
__device__ __align__(16) __half g_wvh16[FF * FF];
__device__ __align__(16) __half g_wo16 [FF * FF];
__device__ __align__(16) __half g_wf116[FF * FF];
__device__ __align__(16) __half g_wf216[FF * FF];

// ------------------- asm helpers -------------------
__device__ __forceinline__ unsigned sptr(const void* ptr) {
    return (unsigned)__cvta_generic_to_shared(ptr);
}
__device__ __forceinline__ void ldsm4(unsigned& r0, unsigned& r1, unsigned& r2, unsigned& r3, unsigned addr) {
    asm volatile("ldmatrix.sync.aligned.m8n8.x4.shared.b16 {%0,%1,%2,%3},[%4];"
                 : "=r"(r0), "=r"(r1), "=r"(r2), "=r"(r3) : "r"(addr));
}
__device__ __forceinline__ void ldsm4t(unsigned& r0, unsigned& r1, unsigned& r2, unsigned& r3, unsigned addr) {
    asm volatile("ldmatrix.sync.aligned.m8n8.x4.trans.shared.b16 {%0,%1,%2,%3},[%4];"
                 : "=r"(r0), "=r"(r1), "=r"(r2), "=r"(r3) : "r"(addr));
}
__device__ __forceinline__ void mma16816(float* cc, const unsigned* aa, const unsigned* bb) {
    asm volatile("mma.sync.aligned.m16n8k16.row.col.f32.f16.f16.f32 "
                 "{%0,%1,%2,%3},{%4,%5,%6,%7},{%8,%9},{%0,%1,%2,%3};"
                 : "+f"(cc[0]), "+f"(cc[1]), "+f"(cc[2]), "+f"(cc[3])
                 : "r"(aa[0]), "r"(aa[1]), "r"(aa[2]), "r"(aa[3]), "r"(bb[0]), "r"(bb[1]));
}
__device__ __forceinline__ unsigned pack2(float a, float b) {
    __half2 h = __floats2half2_rn(a, b);
    return *reinterpret_cast<unsigned*>(&h);
}
__device__ __forceinline__ void cpa16(void* dst, const void* src) {
    asm volatile("cp.async.cg.shared.global [%0], [%1], 16;"
                 :: "r"(sptr(dst)), "l"(src));
}
__device__ __forceinline__ void cpcommit() {
    asm volatile("cp.async.commit_group;");
}
template<int N> __device__ __forceinline__ void cpwait() {
    asm volatile("cp.async.wait_group %0;" :: "n"(N));
}

// ---------- 256-thread (8-warp) tile GEMM: warp computes 64x32 ----------
__device__ __forceinline__ void mma_tile(const __half* Amat, const __half* Bmat, float acc[4][4][4]) {
    const int lane = threadIdx.x & 31;
    const int warp = threadIdx.x >> 5;
    const int wy = warp >> 2;
    const int wx = warp & 3;
    const int r16 = lane & 15;
    const int hi8 = (lane >> 4) * 8;
    #pragma unroll
    for (int k0 = 0; k0 < 128; k0 += 16) {
        unsigned afrag[4][4];
        #pragma unroll
        for (int i = 0; i < 4; ++i) {
            unsigned addr = sptr(Amat + (wy * 64 + i * 16 + r16) * HP + k0 + hi8);
            ldsm4(afrag[i][0], afrag[i][1], afrag[i][2], afrag[i][3], addr);
        }
        unsigned bfrag[4][2];
        #pragma unroll
        for (int jj = 0; jj < 2; ++jj) {
            unsigned addr = sptr(Bmat + (k0 + r16) * HP + wx * 32 + jj * 16 + hi8);
            unsigned t0, t1, t2, t3;
            ldsm4t(t0, t1, t2, t3, addr);
            bfrag[jj * 2 + 0][0] = t0; bfrag[jj * 2 + 0][1] = t1;
            bfrag[jj * 2 + 1][0] = t2; bfrag[jj * 2 + 1][1] = t3;
        }
        #pragma unroll
        for (int i = 0; i < 4; ++i)
            #pragma unroll
            for (int j = 0; j < 4; ++j)
                mma16816(acc[i][j], afrag[i], bfrag[j]);
    }
}

// ---------- 512-thread (16-warp) tile GEMM: warp computes 32x32 ----------
__device__ __forceinline__ void mma_tile512(const __half* Amat, const __half* Bmat, float acc[2][4][4]) {
    const int lane = threadIdx.x & 31;
    const int warp = threadIdx.x >> 5;
    const int wy = warp >> 2;
    const int wx = warp & 3;
    const int r16 = lane & 15;
    const int hi8 = (lane >> 4) * 8;
    #pragma unroll
    for (int k0 = 0; k0 < 128; k0 += 16) {
        unsigned afrag[2][4];
        #pragma unroll
        for (int i = 0; i < 2; ++i) {
            unsigned addr = sptr(Amat + (wy * 32 + i * 16 + r16) * HP + k0 + hi8);
            ldsm4(afrag[i][0], afrag[i][1], afrag[i][2], afrag[i][3], addr);
        }
        unsigned bfrag[4][2];
        #pragma unroll
        for (int jj = 0; jj < 2; ++jj) {
            unsigned addr = sptr(Bmat + (k0 + r16) * HP + wx * 32 + jj * 16 + hi8);
            unsigned t0, t1, t2, t3;
            ldsm4t(t0, t1, t2, t3, addr);
            bfrag[jj * 2 + 0][0] = t0; bfrag[jj * 2 + 0][1] = t1;
            bfrag[jj * 2 + 1][0] = t2; bfrag[jj * 2 + 1][1] = t3;
        }
        #pragma unroll
        for (int i = 0; i < 2; ++i)
            #pragma unroll
            for (int j = 0; j < 4; ++j)
                mma16816(acc[i][j], afrag[i], bfrag[j]);
    }
}

__device__ __forceinline__ void store_tile512(__half* dst, float acc[2][4][4],
                                              const float* __restrict__ bias, bool doRelu) {
    const int lane = threadIdx.x & 31;
    const int warp = threadIdx.x >> 5;
    const int wy = warp >> 2;
    const int wx = warp & 3;
    const int gid = lane >> 2;
    const int tig = lane & 3;
    #pragma unroll
    for (int i = 0; i < 2; ++i) {
        int row = wy * 32 + i * 16 + gid;
        #pragma unroll
        for (int j = 0; j < 4; ++j) {
            int col = wx * 32 + j * 8 + tig * 2;
            float2 bv = *(const float2*)(bias + col);
            float o0 = acc[i][j][0] + bv.x;
            float o1 = acc[i][j][1] + bv.y;
            float o2 = acc[i][j][2] + bv.x;
            float o3 = acc[i][j][3] + bv.y;
            if (doRelu) {
                o0 = fmaxf(o0, 0.f); o1 = fmaxf(o1, 0.f);
                o2 = fmaxf(o2, 0.f); o3 = fmaxf(o3, 0.f);
            }
            *(__half2*)(dst + row * HP + col)       = __floats2half2_rn(o0, o1);
            *(__half2*)(dst + (row + 8) * HP + col) = __floats2half2_rn(o2, o3);
        }
    }
}

__device__ __forceinline__ void store_tile(__half* dst, float acc[4][4][4],
                                           const float* __restrict__ bias, bool doRelu) {
    const int lane = threadIdx.x & 31;
    const int warp = threadIdx.x >> 5;
    const int wy = warp >> 2;
    const int wx = warp & 3;
    const int gid = lane >> 2;
    const int tig = lane & 3;
    #pragma unroll
    for (int i = 0; i < 4; ++i) {
        int row = wy * 64 + i * 16 + gid;
        #pragma unroll
        for (int j = 0; j < 4; ++j) {
            int col = wx * 32 + j * 8 + tig * 2;
            float2 bv = *(const float2*)(bias + col);
            float o0 = acc[i][j][0] + bv.x;
            float o1 = acc[i][j][1] + bv.y;
            float o2 = acc[i][j][2] + bv.x;
            float o3 = acc[i][j][3] + bv.y;
            if (doRelu) {
                o0 = fmaxf(o0, 0.f); o1 = fmaxf(o1, 0.f);
                o2 = fmaxf(o2, 0.f); o3 = fmaxf(o3, 0.f);
            }
            *(__half2*)(dst + row * HP + col)       = __floats2half2_rn(o0, o1);
            *(__half2*)(dst + (row + 8) * HP + col) = __floats2half2_rn(o2, o3);
        }
    }
}

// =====================================================================
// Kernel 0: one-time fp32 -> fp16 weight conversion (vectorized).
// =====================================================================
__global__ void conv_kernel(const float* __restrict__ Wq, const float* __restrict__ Wkh,
                            const float* __restrict__ Wvh, const float* __restrict__ Wo,
                            const float* __restrict__ Wf1, const float* __restrict__ Wf2)
{
    int i = blockIdx.x * 256 + threadIdx.x;   // i in [0, 4096): one float4 per array
    float4 a;
    a = ((const float4*)Wq)[i];
    ((__half2*)g_wq16)[2 * i]     = __floats2half2_rn(a.x, a.y);
    ((__half2*)g_wq16)[2 * i + 1] = __floats2half2_rn(a.z, a.w);
    a = ((const float4*)Wkh)[i];
    ((__half2*)g_wkh16)[2 * i]     = __floats2half2_rn(a.x, a.y);
    ((__half2*)g_wkh16)[2 * i + 1] = __floats2half2_rn(a.z, a.w);
    a = ((const float4*)Wvh)[i];
    ((__half2*)g_wvh16)[2 * i]     = __floats2half2_rn(a.x, a.y);
    ((__half2*)g_wvh16)[2 * i + 1] = __floats2half2_rn(a.z, a.w);
    a = ((const float4*)Wo)[i];
    ((__half2*)g_wo16)[2 * i]     = __floats2half2_rn(a.x, a.y);
    ((__half2*)g_wo16)[2 * i + 1] = __floats2half2_rn(a.z, a.w);
    a = ((const float4*)Wf1)[i];
    ((__half2*)g_wf116)[2 * i]     = __floats2half2_rn(a.x, a.y);
    ((__half2*)g_wf116)[2 * i + 1] = __floats2half2_rn(a.z, a.w);
    a = ((const float4*)Wf2)[i];
    ((__half2*)g_wf216)[2 * i]     = __floats2half2_rn(a.x, a.y);
    ((__half2*)g_wf216)[2 * i + 1] = __floats2half2_rn(a.z, a.w);
}

// =====================================================================
// Split attention warp body (unchanged from R8).
// =====================================================================
template<int G, int H>
__device__ __forceinline__ void attn_half(const __half* Qs, const __half* Ks, const __half* Vs,
                                          __half* B1, float* pm, float* pl,
                                          int base, int lane)
{
    constexpr int NT = G + 1;
    constexpr int JS0 = (H == 0) ? 0 : (G + 1);
    constexpr int NPAIR = (NT + 1) / 2;
    const int r16 = lane & 15;
    const int hi8 = (lane >> 4) * 8;
    const int gid = lane >> 2;
    const int tig = lane & 3;
    const int tlo = 16 * G + gid;
    const int thi = tlo + 8;

    float c[NT][4];
    #pragma unroll
    for (int jt = 0; jt < NT; ++jt) { c[jt][0] = 0.f; c[jt][1] = 0.f; c[jt][2] = 0.f; c[jt][3] = 0.f; }

    #pragma unroll
    for (int k = 0; k < 8; ++k) {
        unsigned aq[4];
        ldsm4(aq[0], aq[1], aq[2], aq[3], sptr(Qs + (16 * G + r16) * HP + k * 16 + hi8));
        #pragma unroll
        for (int jp = 0; jp < NPAIR; ++jp) {
            unsigned t0, t1, t2, t3;
            ldsm4(t0, t1, t2, t3, sptr(Ks + (8 * JS0 + 16 * jp + r16) * HP + k * 16 + hi8));
            unsigned bE[2] = { t0, t2 };
            mma16816(c[2 * jp], aq, bE);
            if (2 * jp + 1 < NT) {
                unsigned bO[2] = { t1, t3 };
                mma16816(c[2 * jp + 1], aq, bO);
            }
        }
    }

    const float scale = 0.08838834764831845f;
    float mlo = -1e30f, mhi = -1e30f;
    #pragma unroll
    for (int jt = 0; jt < NT; ++jt) {
        int s0 = 8 * (JS0 + jt) + 2 * tig;
        int s1 = s0 + 1;
        float v0 = c[jt][0] * scale;
        float v1 = c[jt][1] * scale;
        float v2 = c[jt][2] * scale;
        float v3 = c[jt][3] * scale;
        if (s0 > tlo) v0 = -1e30f;
        if (s1 > tlo) v1 = -1e30f;
        if (s0 > thi) v2 = -1e30f;
        if (s1 > thi) v3 = -1e30f;
        c[jt][0] = v0; c[jt][1] = v1; c[jt][2] = v2; c[jt][3] = v3;
        mlo = fmaxf(mlo, fmaxf(v0, v1));
        mhi = fmaxf(mhi, fmaxf(v2, v3));
    }
    #pragma unroll
    for (int o = 1; o <= 2; o <<= 1) {
        mlo = fmaxf(mlo, __shfl_xor_sync(0xffffffffu, mlo, o));
        mhi = fmaxf(mhi, __shfl_xor_sync(0xffffffffu, mhi, o));
    }
    float slo = 0.f, shi = 0.f;
    #pragma unroll
    for (int jt = 0; jt < NT; ++jt) {
        c[jt][0] = __expf(c[jt][0] - mlo);
        c[jt][1] = __expf(c[jt][1] - mlo);
        c[jt][2] = __expf(c[jt][2] - mhi);
        c[jt][3] = __expf(c[jt][3] - mhi);
        slo += c[jt][0] + c[jt][1];
        shi += c[jt][2] + c[jt][3];
    }
    #pragma unroll
    for (int o = 1; o <= 2; o <<= 1) {
        slo += __shfl_xor_sync(0xffffffffu, slo, o);
        shi += __shfl_xor_sync(0xffffffffu, shi, o);
    }
    if (tig == 0) {
        pm[H * 128 + tlo] = mlo;  pl[H * 128 + tlo] = slo;
        pm[H * 128 + thi] = mhi;  pl[H * 128 + thi] = shi;
    }
    __syncthreads();   // (1) exchange m/l

    float m0lo = pm[tlo], m1lo = pm[128 + tlo];
    float m0hi = pm[thi], m1hi = pm[128 + thi];
    float mglo = fmaxf(m0lo, m1lo);
    float mghi = fmaxf(m0hi, m1hi);
    float lglo = pl[tlo] * __expf(m0lo - mglo) + pl[128 + tlo] * __expf(m1lo - mglo);
    float lghi = pl[thi] * __expf(m0hi - mghi) + pl[128 + thi] * __expf(m1hi - mghi);
    float alo = __expf((H == 0 ? m0lo : m1lo) - mglo);
    float ahi = __expf((H == 0 ? m0hi : m1hi) - mghi);
    float invlo = 1.f / lglo;
    float invhi = 1.f / lghi;

    float ov[16][4];
    #pragma unroll
    for (int jt = 0; jt < 16; ++jt) { ov[jt][0] = 0.f; ov[jt][1] = 0.f; ov[jt][2] = 0.f; ov[jt][3] = 0.f; }

    #pragma unroll
    for (int kp = 0; kp < NPAIR; ++kp) {
        unsigned ap[4];
        ap[0] = pack2(c[2 * kp][0], c[2 * kp][1]);
        ap[1] = pack2(c[2 * kp][2], c[2 * kp][3]);
        if (2 * kp + 1 < NT) {
            ap[2] = pack2(c[2 * kp + 1][0], c[2 * kp + 1][1]);
            ap[3] = pack2(c[2 * kp + 1][2], c[2 * kp + 1][3]);
        } else {
            ap[2] = 0u; ap[3] = 0u;
        }
        #pragma unroll
        for (int jfp = 0; jfp < 8; ++jfp) {
            unsigned t0, t1, t2, t3;
            ldsm4t(t0, t1, t2, t3, sptr(Vs + (8 * JS0 + 16 * kp + r16) * HP + jfp * 16 + hi8));
            unsigned b0[2] = { t0, t1 };
            unsigned b1[2] = { t2, t3 };
            mma16816(ov[2 * jfp],     ap, b0);
            mma16816(ov[2 * jfp + 1], ap, b1);
        }
    }

    if (H == 1) {
        #pragma unroll
        for (int jt = 0; jt < 16; ++jt) {
            int col = jt * 8 + tig * 2;
            *(__half2*)(B1 + tlo * HP + col) = __floats2half2_rn(ov[jt][0] * alo, ov[jt][1] * alo);
            *(__half2*)(B1 + thi * HP + col) = __floats2half2_rn(ov[jt][2] * ahi, ov[jt][3] * ahi);
        }
    }
    __syncthreads();   // (2) partial O visible

    if (H == 0) {
        __half* olo = g_attn + (base + tlo * NN) * FF;
        __half* ohi = g_attn + (base + thi * NN) * FF;
        #pragma unroll
        for (int jt = 0; jt < 16; ++jt) {
            int col = jt * 8 + tig * 2;
            float2 p0 = __half22float2(*(const __half2*)(B1 + tlo * HP + col));
            float2 p1 = __half22float2(*(const __half2*)(B1 + thi * HP + col));
            float o0 = (ov[jt][0] * alo + p0.x) * invlo;
            float o1 = (ov[jt][1] * alo + p0.y) * invlo;
            float o2 = (ov[jt][2] * ahi + p1.x) * invhi;
            float o3 = (ov[jt][3] * ahi + p1.y) * invhi;
            *(__half2*)(olo + col) = __floats2half2_rn(o0, o1);
            *(__half2*)(ohi + col) = __floats2half2_rn(o2, o3);
        }
    }
}

// =====================================================================
// Kernel 1 (fused qkv + attention), one head per CTA, 512 threads.
// cp.async weight staging overlapped with X-convert staging.
// =====================================================================
__global__ __launch_bounds__(512, 1) void fused_attn_kernel(
    const float* __restrict__ xl, const float* __restrict__ xh,
    const float* __restrict__ te,
    const float* __restrict__ bq, const float* __restrict__ bkh,
    const float* __restrict__ bvh)
{
    extern __shared__ char smraw[];
    __half* X1 = (__half*)smraw;          // xh+te -> later Q
    __half* X2 = X1 + 128 * HP;           // xl+te -> later B1
    __half* W0 = X2 + 128 * HP;           // Wkh -> Wq
    __half* W1 = W0 + 128 * HP;           // Wvh
    __half* Ks = W1 + 128 * HP;
    __half* Vs = Ks + 128 * HP;
    float* pm = (float*)(Vs + 128 * HP);  // [2][128]
    float* pl = pm + 256;                 // [2][128]

    const int head = blockIdx.x;
    const int bidx = head >> 8;
    const int nidx = head & 255;
    const int base = bidx * TT * NN + nidx;

    const int tid = threadIdx.x;
    const int ww = tid >> 5;
    const int lane = tid & 31;

    const float4* xl4 = (const float4*)xl;
    const float4* xh4 = (const float4*)xh;
    const float4* te4 = (const float4*)te;

    // ---- weights via cp.async (issued first, overlap with X staging) ----
    #pragma unroll
    for (int v = tid; v < 2048; v += 512) {
        int row = v >> 4;
        int q16 = v & 15;
        cpa16(W0 + row * HP + q16 * 8, ((const uint4*)g_wkh16) + row * 16 + q16);
        cpa16(W1 + row * HP + q16 * 8, ((const uint4*)g_wvh16) + row * 16 + q16);
    }
    cpcommit();

    // ---- X staging (fully unrolled for MLP) ----
    #pragma unroll
    for (int v = tid; v < 4096; v += 512) {
        int row = v >> 5;
        int c4 = v & 31;
        float4 tval = te4[(bidx * TT + row) * 32 + c4];
        float4 ah = xh4[(base + row * NN) * 32 + c4];
        __half2* dh = (__half2*)(X1 + row * HP + c4 * 4);
        dh[0] = __floats2half2_rn(ah.x + tval.x, ah.y + tval.y);
        dh[1] = __floats2half2_rn(ah.z + tval.z, ah.w + tval.w);
        float4 al = xl4[(base + row * NN) * 32 + c4];
        __half2* dl = (__half2*)(X2 + row * HP + c4 * 4);
        dl[0] = __floats2half2_rn(al.x + tval.x, al.y + tval.y);
        dl[1] = __floats2half2_rn(al.z + tval.z, al.w + tval.w);
    }
    cpwait<0>();
    __syncthreads();

    // ---- K, V GEMMs ----
    {
        float accK[2][4][4] = {};
        mma_tile512(X1, W0, accK);
        float accV[2][4][4] = {};
        mma_tile512(X1, W1, accV);
        __syncthreads();                 // X1/W0/W1 reads done

        // prefetch Wq into W0 while storing K/V tiles
        #pragma unroll
        for (int v = tid; v < 2048; v += 512) {
            int row = v >> 4;
            int q16 = v & 15;
            cpa16(W0 + row * HP + q16 * 8, ((const uint4*)g_wq16) + row * 16 + q16);
        }
        cpcommit();

        store_tile512(Ks, accK, bkh, true);
        store_tile512(Vs, accV, bvh, true);
    }
    cpwait<0>();
    __syncthreads();

    // ---- Q GEMM -> X1 ----
    {
        float accQ[2][4][4] = {};
        mma_tile512(X2, W0, accQ);
        store_tile512(X1, accQ, bq, false);
    }
    __syncthreads();                      // Q/K/V visible; X2 free -> B1

    // ---- split causal attention ----
    const int G = ww >> 1;
    const int H = ww & 1;
    switch (G * 2 + H) {
        case 0:  attn_half<0, 0>(X1, Ks, Vs, X2, pm, pl, base, lane); break;
        case 1:  attn_half<0, 1>(X1, Ks, Vs, X2, pm, pl, base, lane); break;
        case 2:  attn_half<1, 0>(X1, Ks, Vs, X2, pm, pl, base, lane); break;
        case 3:  attn_half<1, 1>(X1, Ks, Vs, X2, pm, pl, base, lane); break;
        case 4:  attn_half<2, 0>(X1, Ks, Vs, X2, pm, pl, base, lane); break;
        case 5:  attn_half<2, 1>(X1, Ks, Vs, X2, pm, pl, base, lane); break;
        case 6:  attn_half<3, 0>(X1, Ks, Vs, X2, pm, pl, base, lane); break;
        case 7:  attn_half<3, 1>(X1, Ks, Vs, X2, pm, pl, base, lane); break;
        case 8:  attn_half<4, 0>(X1, Ks, Vs, X2, pm, pl, base, lane); break;
        case 9:  attn_half<4, 1>(X1, Ks, Vs, X2, pm, pl, base, lane); break;
        case 10: attn_half<5, 0>(X1, Ks, Vs, X2, pm, pl, base, lane); break;
        case 11: attn_half<5, 1>(X1, Ks, Vs, X2, pm, pl, base, lane); break;
        case 12: attn_half<6, 0>(X1, Ks, Vs, X2, pm, pl, base, lane); break;
        case 13: attn_half<6, 1>(X1, Ks, Vs, X2, pm, pl, base, lane); break;
        case 14: attn_half<7, 0>(X1, Ks, Vs, X2, pm, pl, base, lane); break;
        default: attn_half<7, 1>(X1, Ks, Vs, X2, pm, pl, base, lane); break;
    }
}

// =====================================================================
// Kernel 2 (fused proj+ffn), 256 threads, 2 CTAs/SM.
// cp.async prefetch: Wf1 -> A2 (at start), Wf2 -> Wb (after proj GEMM).
// h goes into A2 (ln1 stays in A1 for residual).
// =====================================================================
__global__ __launch_bounds__(256, 2) void tail_kernel(
    float* __restrict__ outp,
    const float* __restrict__ xl, const float* __restrict__ te,
    const float* __restrict__ bo, const float* __restrict__ bf1,
    const float* __restrict__ bf2)
{
    extern __shared__ char smraw[];
    __half* A1 = (__half*)smraw;          // attn -> ln1 (f16)
    __half* A2 = A1 + 128 * HP;           // Wf1 -> h
    __half* Wb = A2 + 128 * HP;           // Wo -> Wf2
    float* red1 = (float*)(Wb + 128 * HP);   // [128][4] sums
    float* red2 = red1 + 512;                // [128][4] sumsq

    const int m0 = blockIdx.x * 128;
    const int tid = threadIdx.x;
    const float* teRow = te + (m0 / NN) * FF;

    // prefetch Wf1 into A2 (async)
    #pragma unroll
    for (int v = tid; v < 2048; v += 256) {
        int row = v >> 4;
        int q16 = v & 15;
        cpa16(A2 + row * HP + q16 * 8, ((const uint4*)g_wf116) + row * 16 + q16);
    }
    cpcommit();

    // stage attn tile + Wo
    #pragma unroll
    for (int v = tid; v < 2048; v += 256) {
        int row = v >> 4;
        int q16 = v & 15;
        ((uint4*)(A1 + row * HP))[q16] = ((const uint4*)(g_attn + (m0 + row) * FF))[q16];
        ((uint4*)(Wb + row * HP))[q16] = ((const uint4*)g_wo16)[row * 16 + q16];
    }
    __syncthreads();

    const int lane = tid & 31;
    const int warp = tid >> 5;
    const int wy = warp >> 2;
    const int wx = warp & 3;
    const int gid = lane >> 2;
    const int tig = lane & 3;

    // ---- proj GEMM ----
    float acc[4][4][4] = {};
    mma_tile(A1, Wb, acc);
    __syncthreads();   // A1/Wb reads done

    // prefetch Wf2 into Wb (async; consumed at GEMM2)
    #pragma unroll
    for (int v = tid; v < 2048; v += 256) {
        int row = v >> 4;
        int q16 = v & 15;
        cpa16(Wb + row * HP + q16 * 8, ((const uint4*)g_wf216) + row * 16 + q16);
    }
    cpcommit();

    // ---- val = acc + bo + xl + te ; LN1 partials ----
    #pragma unroll
    for (int i = 0; i < 4; ++i) {
        int rlo = wy * 64 + i * 16 + gid;
        int rhi = rlo + 8;
        float s1lo = 0.f, s2lo = 0.f, s1hi = 0.f, s2hi = 0.f;
        #pragma unroll
        for (int j = 0; j < 4; ++j) {
            int col = wx * 32 + j * 8 + tig * 2;
            float2 bv = *(const float2*)(bo + col);
            float2 x0 = *(const float2*)(xl + (m0 + rlo) * FF + col);
            float2 x1 = *(const float2*)(xl + (m0 + rhi) * FF + col);
            float2 t0 = *(const float2*)(teRow + col);
            float v0 = acc[i][j][0] + bv.x + x0.x + t0.x;
            float v1 = acc[i][j][1] + bv.y + x0.y + t0.y;
            float v2 = acc[i][j][2] + bv.x + x1.x + t0.x;
            float v3 = acc[i][j][3] + bv.y + x1.y + t0.y;
            acc[i][j][0] = v0; acc[i][j][1] = v1;
            acc[i][j][2] = v2; acc[i][j][3] = v3;
            s1lo += v0 + v1; s2lo += v0 * v0 + v1 * v1;
            s1hi += v2 + v3; s2hi += v2 * v2 + v3 * v3;
        }
        #pragma unroll
        for (int o = 1; o <= 2; o <<= 1) {
            s1lo += __shfl_xor_sync(0xffffffffu, s1lo, o);
            s2lo += __shfl_xor_sync(0xffffffffu, s2lo, o);
            s1hi += __shfl_xor_sync(0xffffffffu, s1hi, o);
            s2hi += __shfl_xor_sync(0xffffffffu, s2hi, o);
        }
        if (tig == 0) {
            red1[rlo * 4 + wx] = s1lo; red2[rlo * 4 + wx] = s2lo;
            red1[rhi * 4 + wx] = s1hi; red2[rhi * 4 + wx] = s2hi;
        }
    }
    __syncthreads();

    // ---- LN1 finalize -> ln1 (f16) into A1 ----
    #pragma unroll
    for (int i = 0; i < 4; ++i) {
        int rlo = wy * 64 + i * 16 + gid;
        int rhi = rlo + 8;
        float mlo = (red1[rlo * 4] + red1[rlo * 4 + 1] + red1[rlo * 4 + 2] + red1[rlo * 4 + 3]) * 0.0078125f;
        float vlo = (red2[rlo * 4] + red2[rlo * 4 + 1] + red2[rlo * 4 + 2] + red2[rlo * 4 + 3]) * 0.0078125f - mlo * mlo;
        float rslo = rsqrtf(vlo + 1e-5f);
        float mhi = (red1[rhi * 4] + red1[rhi * 4 + 1] + red1[rhi * 4 + 2] + red1[rhi * 4 + 3]) * 0.0078125f;
        float vhi = (red2[rhi * 4] + red2[rhi * 4 + 1] + red2[rhi * 4 + 2] + red2[rhi * 4 + 3]) * 0.0078125f - mhi * mhi;
        float rshi = rsqrtf(vhi + 1e-5f);
        #pragma unroll
        for (int j = 0; j < 4; ++j) {
            int col = wx * 32 + j * 8 + tig * 2;
            *(__half2*)(A1 + rlo * HP + col) =
                __floats2half2_rn((acc[i][j][0] - mlo) * rslo, (acc[i][j][1] - mlo) * rslo);
            *(__half2*)(A1 + rhi * HP + col) =
                __floats2half2_rn((acc[i][j][2] - mhi) * rshi, (acc[i][j][3] - mhi) * rshi);
        }
    }
    cpwait<1>();       // Wf1 (group 0) complete
    __syncthreads();   // ln1 + Wf1 visible

    // ---- FFN GEMM 1: h = relu(ln1 @ Wf1 + bf1) ----
    float acc2[4][4][4] = {};
    mma_tile(A1, A2, acc2);
    __syncthreads();   // A2 (Wf1) reads done
    store_tile(A2, acc2, bf1, true);      // h -> A2 (ln1 stays in A1)
    cpwait<0>();       // Wf2 complete
    __syncthreads();

    // ---- FFN GEMM 2: h2 = h @ Wf2 ----
    float acc3[4][4][4] = {};
    mma_tile(A2, Wb, acc3);

    // ---- acc3 += bf2 + ln1(A1); LN2 partials ----
    #pragma unroll
    for (int i = 0; i < 4; ++i) {
        int rlo = wy * 64 + i * 16 + gid;
        int rhi = rlo + 8;
        float s1lo = 0.f, s2lo = 0.f, s1hi = 0.f, s2hi = 0.f;
        #pragma unroll
        for (int j = 0; j < 4; ++j) {
            int col = wx * 32 + j * 8 + tig * 2;
            float2 bv = *(const float2*)(bf2 + col);
            float2 l0 = __half22float2(*(const __half2*)(A1 + rlo * HP + col));
            float2 l1 = __half22float2(*(const __half2*)(A1 + rhi * HP + col));
            float v0 = acc3[i][j][0] + bv.x + l0.x;
            float v1 = acc3[i][j][1] + bv.y + l0.y;
            float v2 = acc3[i][j][2] + bv.x + l1.x;
            float v3 = acc3[i][j][3] + bv.y + l1.y;
            acc3[i][j][0] = v0; acc3[i][j][1] = v1;
            acc3[i][j][2] = v2; acc3[i][j][3] = v3;
            s1lo += v0 + v1; s2lo += v0 * v0 + v1 * v1;
            s1hi += v2 + v3; s2hi += v2 * v2 + v3 * v3;
        }
        #pragma unroll
        for (int o = 1; o <= 2; o <<= 1) {
            s1lo += __shfl_xor_sync(0xffffffffu, s1lo, o);
            s2lo += __shfl_xor_sync(0xffffffffu, s2lo, o);
            s1hi += __shfl_xor_sync(0xffffffffu, s1hi, o);
            s2hi += __shfl_xor_sync(0xffffffffu, s2hi, o);
        }
        if (tig == 0) {
            red1[rlo * 4 + wx] = s1lo; red2[rlo * 4 + wx] = s2lo;
            red1[rhi * 4 + wx] = s1hi; red2[rhi * 4 + wx] = s2hi;
        }
    }
    __syncthreads();

    // ---- LN2 finalize -> output ----
    #pragma unroll
    for (int i = 0; i < 4; ++i) {
        int rlo = wy * 64 + i * 16 + gid;
        int rhi = rlo + 8;
        float mlo = (red1[rlo * 4] + red1[rlo * 4 + 1] + red1[rlo * 4 + 2] + red1[rlo * 4 + 3]) * 0.0078125f;
        float vlo = (red2[rlo * 4] + red2[rlo * 4 + 1] + red2[rlo * 4 + 2] + red2[rlo * 4 + 3]) * 0.0078125f - mlo * mlo;
        float rslo = rsqrtf(vlo + 1e-5f);
        float mhi = (red1[rhi * 4] + red1[rhi * 4 + 1] + red1[rhi * 4 + 2] + red1[rhi * 4 + 3]) * 0.0078125f;
        float vhi = (red2[rhi * 4] + red2[rhi * 4 + 1] + red2[rhi * 4 + 2] + red2[rhi * 4 + 3]) * 0.0078125f - mhi * mhi;
        float rshi = rsqrtf(vhi + 1e-5f);
        #pragma unroll
        for (int j = 0; j < 4; ++j) {
            int col = wx * 32 + j * 8 + tig * 2;
            float2 o0, o1;
            o0.x = (acc3[i][j][0] - mlo) * rslo;
            o0.y = (acc3[i][j][1] - mlo) * rslo;
            o1.x = (acc3[i][j][2] - mhi) * rshi;
            o1.y = (acc3[i][j][3] - mhi) * rshi;
            *(float2*)(outp + (m0 + rlo) * FF + col) = o0;
            *(float2*)(outp + (m0 + rhi) * FF + col) = o1;
        }
    }
}

// =====================================================================
extern "C" void kernel_launch(void* const* d_in, const int* in_sizes, int n_in,
                              void* d_out, int out_size)
{
    const float* xl  = (const float*)d_in[0];
    const float* xh  = (const float*)d_in[1];
    const float* te  = (const float*)d_in[2];
    const float* Wq  = (const float*)d_in[3];
    const float* bq  = (const float*)d_in[4];
    const float* Wkh = (const float*)d_in[5];
    const float* bkh = (const float*)d_in[6];
    const float* Wvh = (const float*)d_in[7];
    const float* bvh = (const float*)d_in[8];
    const float* Wo  = (const float*)d_in[9];
    const float* bo  = (const float*)d_in[10];
    const float* Wf1 = (const float*)d_in[11];
    const float* bf1 = (const float*)d_in[12];
    const float* Wf2 = (const float*)d_in[13];
    const float* bf2 = (const float*)d_in[14];
    float* outp = (float*)d_out;

    const int smFused = 6 * 128 * HP * 2 + 2 * 1024;          // 210944
    const int smTail  = 3 * 128 * HP * 2 + 4096;              // 108544

    cudaFuncSetAttribute(fused_attn_kernel, cudaFuncAttributeMaxDynamicSharedMemorySize, smFused);
    cudaFuncSetAttribute(tail_kernel,       cudaFuncAttributeMaxDynamicSharedMemorySize, smTail);

    conv_kernel<<<16, 256>>>(Wq, Wkh, Wvh, Wo, Wf1, Wf2);
    fused_attn_kernel<<<BB * NN, 512, smFused>>>(xl, xh, te, bq, bkh, bvh);
    tail_kernel<<<MTOT / 128, 256, smTail>>>(outp, xl, te, bo, bf1, bf2);
}

// round 10
// speedup vs baseline: 1.1411x; 1.0455x over previous
#include <cuda_runtime.h>
#include <cuda_fp16.h>
#include <math.h>

constexpr int BB = 8;
constexpr int TT = 128;
constexpr int NN = 256;
constexpr int FF = 128;
constexpr int MTOT = BB * TT * NN;   // 262144
constexpr int HP = 136;              // smem half pitch (padded)

// -------- scratch (device globals) --------
__device__ __half g_attn[MTOT * FF];
__device__ __align__(16) __half g_wq16 [FF * FF];
__device__ __align__(16) __half g_wkh16[FF * FF];
__device__ __align__(16) __half g_wvh16[FF * FF];
__device__ __align__(16) __half g_wo16 [FF * FF];
__device__ __align__(16) __half g_wf116[FF * FF];
__device__ __align__(16) __half g_wf216[FF * FF];

// ------------------- asm helpers -------------------
__device__ __forceinline__ unsigned sptr(const void* ptr) {
    return (unsigned)__cvta_generic_to_shared(ptr);
}
__device__ __forceinline__ void ldsm4(unsigned& r0, unsigned& r1, unsigned& r2, unsigned& r3, unsigned addr) {
    asm volatile("ldmatrix.sync.aligned.m8n8.x4.shared.b16 {%0,%1,%2,%3},[%4];"
                 : "=r"(r0), "=r"(r1), "=r"(r2), "=r"(r3) : "r"(addr));
}
__device__ __forceinline__ void ldsm4t(unsigned& r0, unsigned& r1, unsigned& r2, unsigned& r3, unsigned addr) {
    asm volatile("ldmatrix.sync.aligned.m8n8.x4.trans.shared.b16 {%0,%1,%2,%3},[%4];"
                 : "=r"(r0), "=r"(r1), "=r"(r2), "=r"(r3) : "r"(addr));
}
__device__ __forceinline__ void mma16816(float* cc, const unsigned* aa, const unsigned* bb) {
    asm volatile("mma.sync.aligned.m16n8k16.row.col.f32.f16.f16.f32 "
                 "{%0,%1,%2,%3},{%4,%5,%6,%7},{%8,%9},{%0,%1,%2,%3};"
                 : "+f"(cc[0]), "+f"(cc[1]), "+f"(cc[2]), "+f"(cc[3])
                 : "r"(aa[0]), "r"(aa[1]), "r"(aa[2]), "r"(aa[3]), "r"(bb[0]), "r"(bb[1]));
}
__device__ __forceinline__ unsigned pack2(float a, float b) {
    __half2 h = __floats2half2_rn(a, b);
    return *reinterpret_cast<unsigned*>(&h);
}
__device__ __forceinline__ void cpa16(void* dst, const void* src) {
    asm volatile("cp.async.cg.shared.global [%0], [%1], 16;"
                 :: "r"(sptr(dst)), "l"(src));
}
__device__ __forceinline__ void cpcommit() {
    asm volatile("cp.async.commit_group;");
}
template<int N> __device__ __forceinline__ void cpwait() {
    asm volatile("cp.async.wait_group %0;" :: "n"(N));
}

// ---------- 256-thread (8-warp) tile GEMM: warp computes 64x32 ----------
__device__ __forceinline__ void mma_tile(const __half* Amat, const __half* Bmat, float acc[4][4][4]) {
    const int lane = threadIdx.x & 31;
    const int warp = threadIdx.x >> 5;
    const int wy = warp >> 2;
    const int wx = warp & 3;
    const int r16 = lane & 15;
    const int hi8 = (lane >> 4) * 8;
    #pragma unroll
    for (int k0 = 0; k0 < 128; k0 += 16) {
        unsigned afrag[4][4];
        #pragma unroll
        for (int i = 0; i < 4; ++i) {
            unsigned addr = sptr(Amat + (wy * 64 + i * 16 + r16) * HP + k0 + hi8);
            ldsm4(afrag[i][0], afrag[i][1], afrag[i][2], afrag[i][3], addr);
        }
        unsigned bfrag[4][2];
        #pragma unroll
        for (int jj = 0; jj < 2; ++jj) {
            unsigned addr = sptr(Bmat + (k0 + r16) * HP + wx * 32 + jj * 16 + hi8);
            unsigned t0, t1, t2, t3;
            ldsm4t(t0, t1, t2, t3, addr);
            bfrag[jj * 2 + 0][0] = t0; bfrag[jj * 2 + 0][1] = t1;
            bfrag[jj * 2 + 1][0] = t2; bfrag[jj * 2 + 1][1] = t3;
        }
        #pragma unroll
        for (int i = 0; i < 4; ++i)
            #pragma unroll
            for (int j = 0; j < 4; ++j)
                mma16816(acc[i][j], afrag[i], bfrag[j]);
    }
}

// ---------- 512-thread (16-warp) tile GEMM: warp computes 32x32 ----------
__device__ __forceinline__ void mma_tile512(const __half* Amat, const __half* Bmat, float acc[2][4][4]) {
    const int lane = threadIdx.x & 31;
    const int warp = threadIdx.x >> 5;
    const int wy = warp >> 2;
    const int wx = warp & 3;
    const int r16 = lane & 15;
    const int hi8 = (lane >> 4) * 8;
    #pragma unroll
    for (int k0 = 0; k0 < 128; k0 += 16) {
        unsigned afrag[2][4];
        #pragma unroll
        for (int i = 0; i < 2; ++i) {
            unsigned addr = sptr(Amat + (wy * 32 + i * 16 + r16) * HP + k0 + hi8);
            ldsm4(afrag[i][0], afrag[i][1], afrag[i][2], afrag[i][3], addr);
        }
        unsigned bfrag[4][2];
        #pragma unroll
        for (int jj = 0; jj < 2; ++jj) {
            unsigned addr = sptr(Bmat + (k0 + r16) * HP + wx * 32 + jj * 16 + hi8);
            unsigned t0, t1, t2, t3;
            ldsm4t(t0, t1, t2, t3, addr);
            bfrag[jj * 2 + 0][0] = t0; bfrag[jj * 2 + 0][1] = t1;
            bfrag[jj * 2 + 1][0] = t2; bfrag[jj * 2 + 1][1] = t3;
        }
        #pragma unroll
        for (int i = 0; i < 2; ++i)
            #pragma unroll
            for (int j = 0; j < 4; ++j)
                mma16816(acc[i][j], afrag[i], bfrag[j]);
    }
}

__device__ __forceinline__ void store_tile512(__half* dst, float acc[2][4][4],
                                              const float* __restrict__ bias, bool doRelu) {
    const int lane = threadIdx.x & 31;
    const int warp = threadIdx.x >> 5;
    const int wy = warp >> 2;
    const int wx = warp & 3;
    const int gid = lane >> 2;
    const int tig = lane & 3;
    #pragma unroll
    for (int i = 0; i < 2; ++i) {
        int row = wy * 32 + i * 16 + gid;
        #pragma unroll
        for (int j = 0; j < 4; ++j) {
            int col = wx * 32 + j * 8 + tig * 2;
            float2 bv = *(const float2*)(bias + col);
            float o0 = acc[i][j][0] + bv.x;
            float o1 = acc[i][j][1] + bv.y;
            float o2 = acc[i][j][2] + bv.x;
            float o3 = acc[i][j][3] + bv.y;
            if (doRelu) {
                o0 = fmaxf(o0, 0.f); o1 = fmaxf(o1, 0.f);
                o2 = fmaxf(o2, 0.f); o3 = fmaxf(o3, 0.f);
            }
            *(__half2*)(dst + row * HP + col)       = __floats2half2_rn(o0, o1);
            *(__half2*)(dst + (row + 8) * HP + col) = __floats2half2_rn(o2, o3);
        }
    }
}

__device__ __forceinline__ void store_tile(__half* dst, float acc[4][4][4],
                                           const float* __restrict__ bias, bool doRelu) {
    const int lane = threadIdx.x & 31;
    const int warp = threadIdx.x >> 5;
    const int wy = warp >> 2;
    const int wx = warp & 3;
    const int gid = lane >> 2;
    const int tig = lane & 3;
    #pragma unroll
    for (int i = 0; i < 4; ++i) {
        int row = wy * 64 + i * 16 + gid;
        #pragma unroll
        for (int j = 0; j < 4; ++j) {
            int col = wx * 32 + j * 8 + tig * 2;
            float2 bv = *(const float2*)(bias + col);
            float o0 = acc[i][j][0] + bv.x;
            float o1 = acc[i][j][1] + bv.y;
            float o2 = acc[i][j][2] + bv.x;
            float o3 = acc[i][j][3] + bv.y;
            if (doRelu) {
                o0 = fmaxf(o0, 0.f); o1 = fmaxf(o1, 0.f);
                o2 = fmaxf(o2, 0.f); o3 = fmaxf(o3, 0.f);
            }
            *(__half2*)(dst + row * HP + col)       = __floats2half2_rn(o0, o1);
            *(__half2*)(dst + (row + 8) * HP + col) = __floats2half2_rn(o2, o3);
        }
    }
}

// =====================================================================
// Kernel 0: one-time fp32 -> fp16 weight conversion (vectorized).
// =====================================================================
__global__ void conv_kernel(const float* __restrict__ Wq, const float* __restrict__ Wkh,
                            const float* __restrict__ Wvh, const float* __restrict__ Wo,
                            const float* __restrict__ Wf1, const float* __restrict__ Wf2)
{
    int i = blockIdx.x * 256 + threadIdx.x;
    float4 a;
    a = ((const float4*)Wq)[i];
    ((__half2*)g_wq16)[2 * i]     = __floats2half2_rn(a.x, a.y);
    ((__half2*)g_wq16)[2 * i + 1] = __floats2half2_rn(a.z, a.w);
    a = ((const float4*)Wkh)[i];
    ((__half2*)g_wkh16)[2 * i]     = __floats2half2_rn(a.x, a.y);
    ((__half2*)g_wkh16)[2 * i + 1] = __floats2half2_rn(a.z, a.w);
    a = ((const float4*)Wvh)[i];
    ((__half2*)g_wvh16)[2 * i]     = __floats2half2_rn(a.x, a.y);
    ((__half2*)g_wvh16)[2 * i + 1] = __floats2half2_rn(a.z, a.w);
    a = ((const float4*)Wo)[i];
    ((__half2*)g_wo16)[2 * i]     = __floats2half2_rn(a.x, a.y);
    ((__half2*)g_wo16)[2 * i + 1] = __floats2half2_rn(a.z, a.w);
    a = ((const float4*)Wf1)[i];
    ((__half2*)g_wf116)[2 * i]     = __floats2half2_rn(a.x, a.y);
    ((__half2*)g_wf116)[2 * i + 1] = __floats2half2_rn(a.z, a.w);
    a = ((const float4*)Wf2)[i];
    ((__half2*)g_wf216)[2 * i]     = __floats2half2_rn(a.x, a.y);
    ((__half2*)g_wf216)[2 * i + 1] = __floats2half2_rn(a.z, a.w);
}

// =====================================================================
// Split attention warp body (unchanged).
// =====================================================================
template<int G, int H>
__device__ __forceinline__ void attn_half(const __half* Qs, const __half* Ks, const __half* Vs,
                                          __half* B1, float* pm, float* pl,
                                          int base, int lane)
{
    constexpr int NT = G + 1;
    constexpr int JS0 = (H == 0) ? 0 : (G + 1);
    constexpr int NPAIR = (NT + 1) / 2;
    const int r16 = lane & 15;
    const int hi8 = (lane >> 4) * 8;
    const int gid = lane >> 2;
    const int tig = lane & 3;
    const int tlo = 16 * G + gid;
    const int thi = tlo + 8;

    float c[NT][4];
    #pragma unroll
    for (int jt = 0; jt < NT; ++jt) { c[jt][0] = 0.f; c[jt][1] = 0.f; c[jt][2] = 0.f; c[jt][3] = 0.f; }

    #pragma unroll
    for (int k = 0; k < 8; ++k) {
        unsigned aq[4];
        ldsm4(aq[0], aq[1], aq[2], aq[3], sptr(Qs + (16 * G + r16) * HP + k * 16 + hi8));
        #pragma unroll
        for (int jp = 0; jp < NPAIR; ++jp) {
            unsigned t0, t1, t2, t3;
            ldsm4(t0, t1, t2, t3, sptr(Ks + (8 * JS0 + 16 * jp + r16) * HP + k * 16 + hi8));
            unsigned bE[2] = { t0, t2 };
            mma16816(c[2 * jp], aq, bE);
            if (2 * jp + 1 < NT) {
                unsigned bO[2] = { t1, t3 };
                mma16816(c[2 * jp + 1], aq, bO);
            }
        }
    }

    const float scale = 0.08838834764831845f;
    float mlo = -1e30f, mhi = -1e30f;
    #pragma unroll
    for (int jt = 0; jt < NT; ++jt) {
        int s0 = 8 * (JS0 + jt) + 2 * tig;
        int s1 = s0 + 1;
        float v0 = c[jt][0] * scale;
        float v1 = c[jt][1] * scale;
        float v2 = c[jt][2] * scale;
        float v3 = c[jt][3] * scale;
        if (s0 > tlo) v0 = -1e30f;
        if (s1 > tlo) v1 = -1e30f;
        if (s0 > thi) v2 = -1e30f;
        if (s1 > thi) v3 = -1e30f;
        c[jt][0] = v0; c[jt][1] = v1; c[jt][2] = v2; c[jt][3] = v3;
        mlo = fmaxf(mlo, fmaxf(v0, v1));
        mhi = fmaxf(mhi, fmaxf(v2, v3));
    }
    #pragma unroll
    for (int o = 1; o <= 2; o <<= 1) {
        mlo = fmaxf(mlo, __shfl_xor_sync(0xffffffffu, mlo, o));
        mhi = fmaxf(mhi, __shfl_xor_sync(0xffffffffu, mhi, o));
    }
    float slo = 0.f, shi = 0.f;
    #pragma unroll
    for (int jt = 0; jt < NT; ++jt) {
        c[jt][0] = __expf(c[jt][0] - mlo);
        c[jt][1] = __expf(c[jt][1] - mlo);
        c[jt][2] = __expf(c[jt][2] - mhi);
        c[jt][3] = __expf(c[jt][3] - mhi);
        slo += c[jt][0] + c[jt][1];
        shi += c[jt][2] + c[jt][3];
    }
    #pragma unroll
    for (int o = 1; o <= 2; o <<= 1) {
        slo += __shfl_xor_sync(0xffffffffu, slo, o);
        shi += __shfl_xor_sync(0xffffffffu, shi, o);
    }
    if (tig == 0) {
        pm[H * 128 + tlo] = mlo;  pl[H * 128 + tlo] = slo;
        pm[H * 128 + thi] = mhi;  pl[H * 128 + thi] = shi;
    }
    __syncthreads();   // (1) exchange m/l

    float m0lo = pm[tlo], m1lo = pm[128 + tlo];
    float m0hi = pm[thi], m1hi = pm[128 + thi];
    float mglo = fmaxf(m0lo, m1lo);
    float mghi = fmaxf(m0hi, m1hi);
    float lglo = pl[tlo] * __expf(m0lo - mglo) + pl[128 + tlo] * __expf(m1lo - mglo);
    float lghi = pl[thi] * __expf(m0hi - mghi) + pl[128 + thi] * __expf(m1hi - mghi);
    float alo = __expf((H == 0 ? m0lo : m1lo) - mglo);
    float ahi = __expf((H == 0 ? m0hi : m1hi) - mghi);
    float invlo = 1.f / lglo;
    float invhi = 1.f / lghi;

    float ov[16][4];
    #pragma unroll
    for (int jt = 0; jt < 16; ++jt) { ov[jt][0] = 0.f; ov[jt][1] = 0.f; ov[jt][2] = 0.f; ov[jt][3] = 0.f; }

    #pragma unroll
    for (int kp = 0; kp < NPAIR; ++kp) {
        unsigned ap[4];
        ap[0] = pack2(c[2 * kp][0], c[2 * kp][1]);
        ap[1] = pack2(c[2 * kp][2], c[2 * kp][3]);
        if (2 * kp + 1 < NT) {
            ap[2] = pack2(c[2 * kp + 1][0], c[2 * kp + 1][1]);
            ap[3] = pack2(c[2 * kp + 1][2], c[2 * kp + 1][3]);
        } else {
            ap[2] = 0u; ap[3] = 0u;
        }
        #pragma unroll
        for (int jfp = 0; jfp < 8; ++jfp) {
            unsigned t0, t1, t2, t3;
            ldsm4t(t0, t1, t2, t3, sptr(Vs + (8 * JS0 + 16 * kp + r16) * HP + jfp * 16 + hi8));
            unsigned b0[2] = { t0, t1 };
            unsigned b1[2] = { t2, t3 };
            mma16816(ov[2 * jfp],     ap, b0);
            mma16816(ov[2 * jfp + 1], ap, b1);
        }
    }

    if (H == 1) {
        #pragma unroll
        for (int jt = 0; jt < 16; ++jt) {
            int col = jt * 8 + tig * 2;
            *(__half2*)(B1 + tlo * HP + col) = __floats2half2_rn(ov[jt][0] * alo, ov[jt][1] * alo);
            *(__half2*)(B1 + thi * HP + col) = __floats2half2_rn(ov[jt][2] * ahi, ov[jt][3] * ahi);
        }
    }
    __syncthreads();   // (2) partial O visible

    if (H == 0) {
        __half* olo = g_attn + (base + tlo * NN) * FF;
        __half* ohi = g_attn + (base + thi * NN) * FF;
        #pragma unroll
        for (int jt = 0; jt < 16; ++jt) {
            int col = jt * 8 + tig * 2;
            float2 p0 = __half22float2(*(const __half2*)(B1 + tlo * HP + col));
            float2 p1 = __half22float2(*(const __half2*)(B1 + thi * HP + col));
            float o0 = (ov[jt][0] * alo + p0.x) * invlo;
            float o1 = (ov[jt][1] * alo + p0.y) * invlo;
            float o2 = (ov[jt][2] * ahi + p1.x) * invhi;
            float o3 = (ov[jt][3] * ahi + p1.y) * invhi;
            *(__half2*)(olo + col) = __floats2half2_rn(o0, o1);
            *(__half2*)(ohi + col) = __floats2half2_rn(o2, o3);
        }
    }
}

// =====================================================================
// Kernel 1 (fused qkv + attention), 512 threads, 5-buffer layout.
// All three weights arrive via ONE upfront cp.async batch; no restage.
// Chain: stage -> sync -> KV GEMMs -> sync -> (store K,V; Q GEMM; store Q)
//        -> sync -> attention.
// =====================================================================
__global__ __launch_bounds__(512, 1) void fused_attn_kernel(
    const float* __restrict__ xl, const float* __restrict__ xh,
    const float* __restrict__ te,
    const float* __restrict__ bq, const float* __restrict__ bkh,
    const float* __restrict__ bvh)
{
    extern __shared__ char smraw[];
    __half* X1 = (__half*)smraw;          // xh+te -> later Q
    __half* X2 = X1 + 128 * HP;           // xl+te -> later B1
    __half* W0 = X2 + 128 * HP;           // Wkh   -> later K
    __half* W1 = W0 + 128 * HP;           // Wvh   -> later V
    __half* W2 = W1 + 128 * HP;           // Wq
    float* pm = (float*)(W2 + 128 * HP);  // [2][128]
    float* pl = pm + 256;                 // [2][128]

    const int head = blockIdx.x;
    const int bidx = head >> 8;
    const int nidx = head & 255;
    const int base = bidx * TT * NN + nidx;

    const int tid = threadIdx.x;
    const int ww = tid >> 5;
    const int lane = tid & 31;

    const float4* xl4 = (const float4*)xl;
    const float4* xh4 = (const float4*)xh;
    const float4* te4 = (const float4*)te;

    // ---- all weights via one cp.async batch ----
    #pragma unroll
    for (int v = tid; v < 2048; v += 512) {
        int row = v >> 4;
        int q16 = v & 15;
        cpa16(W0 + row * HP + q16 * 8, ((const uint4*)g_wkh16) + row * 16 + q16);
        cpa16(W1 + row * HP + q16 * 8, ((const uint4*)g_wvh16) + row * 16 + q16);
        cpa16(W2 + row * HP + q16 * 8, ((const uint4*)g_wq16)  + row * 16 + q16);
    }
    cpcommit();

    // ---- X staging (fp32 load + convert), overlapped with weight cp.async ----
    #pragma unroll
    for (int v = tid; v < 4096; v += 512) {
        int row = v >> 5;
        int c4 = v & 31;
        float4 tval = te4[(bidx * TT + row) * 32 + c4];
        float4 ah = xh4[(base + row * NN) * 32 + c4];
        __half2* dh = (__half2*)(X1 + row * HP + c4 * 4);
        dh[0] = __floats2half2_rn(ah.x + tval.x, ah.y + tval.y);
        dh[1] = __floats2half2_rn(ah.z + tval.z, ah.w + tval.w);
        float4 al = xl4[(base + row * NN) * 32 + c4];
        __half2* dl = (__half2*)(X2 + row * HP + c4 * 4);
        dl[0] = __floats2half2_rn(al.x + tval.x, al.y + tval.y);
        dl[1] = __floats2half2_rn(al.z + tval.z, al.w + tval.w);
    }
    cpwait<0>();
    __syncthreads();

    // ---- K, V GEMMs ----
    float accK[2][4][4] = {};
    mma_tile512(X1, W0, accK);
    float accV[2][4][4] = {};
    mma_tile512(X1, W1, accV);
    __syncthreads();                 // all X1/W0/W1 reads done

    // ---- store K->W0buf, V->W1buf; Q GEMM (X2*W2, untouched buffers); Q->X1 ----
    store_tile512(W0, accK, bkh, true);
    store_tile512(W1, accV, bvh, true);
    {
        float accQ[2][4][4] = {};
        mma_tile512(X2, W2, accQ);
        store_tile512(X1, accQ, bq, false);
    }
    __syncthreads();                 // Q/K/V visible; X2 free -> B1

    // ---- split causal attention: Q=X1, K=W0, V=W1, B1=X2 ----
    const int G = ww >> 1;
    const int H = ww & 1;
    switch (G * 2 + H) {
        case 0:  attn_half<0, 0>(X1, W0, W1, X2, pm, pl, base, lane); break;
        case 1:  attn_half<0, 1>(X1, W0, W1, X2, pm, pl, base, lane); break;
        case 2:  attn_half<1, 0>(X1, W0, W1, X2, pm, pl, base, lane); break;
        case 3:  attn_half<1, 1>(X1, W0, W1, X2, pm, pl, base, lane); break;
        case 4:  attn_half<2, 0>(X1, W0, W1, X2, pm, pl, base, lane); break;
        case 5:  attn_half<2, 1>(X1, W0, W1, X2, pm, pl, base, lane); break;
        case 6:  attn_half<3, 0>(X1, W0, W1, X2, pm, pl, base, lane); break;
        case 7:  attn_half<3, 1>(X1, W0, W1, X2, pm, pl, base, lane); break;
        case 8:  attn_half<4, 0>(X1, W0, W1, X2, pm, pl, base, lane); break;
        case 9:  attn_half<4, 1>(X1, W0, W1, X2, pm, pl, base, lane); break;
        case 10: attn_half<5, 0>(X1, W0, W1, X2, pm, pl, base, lane); break;
        case 11: attn_half<5, 1>(X1, W0, W1, X2, pm, pl, base, lane); break;
        case 12: attn_half<6, 0>(X1, W0, W1, X2, pm, pl, base, lane); break;
        case 13: attn_half<6, 1>(X1, W0, W1, X2, pm, pl, base, lane); break;
        case 14: attn_half<7, 0>(X1, W0, W1, X2, pm, pl, base, lane); break;
        default: attn_half<7, 1>(X1, W0, W1, X2, pm, pl, base, lane); break;
    }
}

// =====================================================================
// Kernel 2 (fused proj+ffn), 256 threads, 2 CTAs/SM (unchanged from R9).
// =====================================================================
__global__ __launch_bounds__(256, 2) void tail_kernel(
    float* __restrict__ outp,
    const float* __restrict__ xl, const float* __restrict__ te,
    const float* __restrict__ bo, const float* __restrict__ bf1,
    const float* __restrict__ bf2)
{
    extern __shared__ char smraw[];
    __half* A1 = (__half*)smraw;          // attn -> ln1 (f16)
    __half* A2 = A1 + 128 * HP;           // Wf1 -> h
    __half* Wb = A2 + 128 * HP;           // Wo -> Wf2
    float* red1 = (float*)(Wb + 128 * HP);
    float* red2 = red1 + 512;

    const int m0 = blockIdx.x * 128;
    const int tid = threadIdx.x;
    const float* teRow = te + (m0 / NN) * FF;

    #pragma unroll
    for (int v = tid; v < 2048; v += 256) {
        int row = v >> 4;
        int q16 = v & 15;
        cpa16(A2 + row * HP + q16 * 8, ((const uint4*)g_wf116) + row * 16 + q16);
    }
    cpcommit();

    #pragma unroll
    for (int v = tid; v < 2048; v += 256) {
        int row = v >> 4;
        int q16 = v & 15;
        ((uint4*)(A1 + row * HP))[q16] = ((const uint4*)(g_attn + (m0 + row) * FF))[q16];
        ((uint4*)(Wb + row * HP))[q16] = ((const uint4*)g_wo16)[row * 16 + q16];
    }
    __syncthreads();

    const int lane = tid & 31;
    const int warp = tid >> 5;
    const int wy = warp >> 2;
    const int wx = warp & 3;
    const int gid = lane >> 2;
    const int tig = lane & 3;

    float acc[4][4][4] = {};
    mma_tile(A1, Wb, acc);
    __syncthreads();

    #pragma unroll
    for (int v = tid; v < 2048; v += 256) {
        int row = v >> 4;
        int q16 = v & 15;
        cpa16(Wb + row * HP + q16 * 8, ((const uint4*)g_wf216) + row * 16 + q16);
    }
    cpcommit();

    #pragma unroll
    for (int i = 0; i < 4; ++i) {
        int rlo = wy * 64 + i * 16 + gid;
        int rhi = rlo + 8;
        float s1lo = 0.f, s2lo = 0.f, s1hi = 0.f, s2hi = 0.f;
        #pragma unroll
        for (int j = 0; j < 4; ++j) {
            int col = wx * 32 + j * 8 + tig * 2;
            float2 bv = *(const float2*)(bo + col);
            float2 x0 = *(const float2*)(xl + (m0 + rlo) * FF + col);
            float2 x1 = *(const float2*)(xl + (m0 + rhi) * FF + col);
            float2 t0 = *(const float2*)(teRow + col);
            float v0 = acc[i][j][0] + bv.x + x0.x + t0.x;
            float v1 = acc[i][j][1] + bv.y + x0.y + t0.y;
            float v2 = acc[i][j][2] + bv.x + x1.x + t0.x;
            float v3 = acc[i][j][3] + bv.y + x1.y + t0.y;
            acc[i][j][0] = v0; acc[i][j][1] = v1;
            acc[i][j][2] = v2; acc[i][j][3] = v3;
            s1lo += v0 + v1; s2lo += v0 * v0 + v1 * v1;
            s1hi += v2 + v3; s2hi += v2 * v2 + v3 * v3;
        }
        #pragma unroll
        for (int o = 1; o <= 2; o <<= 1) {
            s1lo += __shfl_xor_sync(0xffffffffu, s1lo, o);
            s2lo += __shfl_xor_sync(0xffffffffu, s2lo, o);
            s1hi += __shfl_xor_sync(0xffffffffu, s1hi, o);
            s2hi += __shfl_xor_sync(0xffffffffu, s2hi, o);
        }
        if (tig == 0) {
            red1[rlo * 4 + wx] = s1lo; red2[rlo * 4 + wx] = s2lo;
            red1[rhi * 4 + wx] = s1hi; red2[rhi * 4 + wx] = s2hi;
        }
    }
    __syncthreads();

    #pragma unroll
    for (int i = 0; i < 4; ++i) {
        int rlo = wy * 64 + i * 16 + gid;
        int rhi = rlo + 8;
        float mlo = (red1[rlo * 4] + red1[rlo * 4 + 1] + red1[rlo * 4 + 2] + red1[rlo * 4 + 3]) * 0.0078125f;
        float vlo = (red2[rlo * 4] + red2[rlo * 4 + 1] + red2[rlo * 4 + 2] + red2[rlo * 4 + 3]) * 0.0078125f - mlo * mlo;
        float rslo = rsqrtf(vlo + 1e-5f);
        float mhi = (red1[rhi * 4] + red1[rhi * 4 + 1] + red1[rhi * 4 + 2] + red1[rhi * 4 + 3]) * 0.0078125f;
        float vhi = (red2[rhi * 4] + red2[rhi * 4 + 1] + red2[rhi * 4 + 2] + red2[rhi * 4 + 3]) * 0.0078125f - mhi * mhi;
        float rshi = rsqrtf(vhi + 1e-5f);
        #pragma unroll
        for (int j = 0; j < 4; ++j) {
            int col = wx * 32 + j * 8 + tig * 2;
            *(__half2*)(A1 + rlo * HP + col) =
                __floats2half2_rn((acc[i][j][0] - mlo) * rslo, (acc[i][j][1] - mlo) * rslo);
            *(__half2*)(A1 + rhi * HP + col) =
                __floats2half2_rn((acc[i][j][2] - mhi) * rshi, (acc[i][j][3] - mhi) * rshi);
        }
    }
    cpwait<1>();       // Wf1 complete
    __syncthreads();

    float acc2[4][4][4] = {};
    mma_tile(A1, A2, acc2);
    __syncthreads();
    store_tile(A2, acc2, bf1, true);
    cpwait<0>();       // Wf2 complete
    __syncthreads();

    float acc3[4][4][4] = {};
    mma_tile(A2, Wb, acc3);

    #pragma unroll
    for (int i = 0; i < 4; ++i) {
        int rlo = wy * 64 + i * 16 + gid;
        int rhi = rlo + 8;
        float s1lo = 0.f, s2lo = 0.f, s1hi = 0.f, s2hi = 0.f;
        #pragma unroll
        for (int j = 0; j < 4; ++j) {
            int col = wx * 32 + j * 8 + tig * 2;
            float2 bv = *(const float2*)(bf2 + col);
            float2 l0 = __half22float2(*(const __half2*)(A1 + rlo * HP + col));
            float2 l1 = __half22float2(*(const __half2*)(A1 + rhi * HP + col));
            float v0 = acc3[i][j][0] + bv.x + l0.x;
            float v1 = acc3[i][j][1] + bv.y + l0.y;
            float v2 = acc3[i][j][2] + bv.x + l1.x;
            float v3 = acc3[i][j][3] + bv.y + l1.y;
            acc3[i][j][0] = v0; acc3[i][j][1] = v1;
            acc3[i][j][2] = v2; acc3[i][j][3] = v3;
            s1lo += v0 + v1; s2lo += v0 * v0 + v1 * v1;
            s1hi += v2 + v3; s2hi += v2 * v2 + v3 * v3;
        }
        #pragma unroll
        for (int o = 1; o <= 2; o <<= 1) {
            s1lo += __shfl_xor_sync(0xffffffffu, s1lo, o);
            s2lo += __shfl_xor_sync(0xffffffffu, s2lo, o);
            s1hi += __shfl_xor_sync(0xffffffffu, s1hi, o);
            s2hi += __shfl_xor_sync(0xffffffffu, s2hi, o);
        }
        if (tig == 0) {
            red1[rlo * 4 + wx] = s1lo; red2[rlo * 4 + wx] = s2lo;
            red1[rhi * 4 + wx] = s1hi; red2[rhi * 4 + wx] = s2hi;
        }
    }
    __syncthreads();

    #pragma unroll
    for (int i = 0; i < 4; ++i) {
        int rlo = wy * 64 + i * 16 + gid;
        int rhi = rlo + 8;
        float mlo = (red1[rlo * 4] + red1[rlo * 4 + 1] + red1[rlo * 4 + 2] + red1[rlo * 4 + 3]) * 0.0078125f;
        float vlo = (red2[rlo * 4] + red2[rlo * 4 + 1] + red2[rlo * 4 + 2] + red2[rlo * 4 + 3]) * 0.0078125f - mlo * mlo;
        float rslo = rsqrtf(vlo + 1e-5f);
        float mhi = (red1[rhi * 4] + red1[rhi * 4 + 1] + red1[rhi * 4 + 2] + red1[rhi * 4 + 3]) * 0.0078125f;
        float vhi = (red2[rhi * 4] + red2[rhi * 4 + 1] + red2[rhi * 4 + 2] + red2[rhi * 4 + 3]) * 0.0078125f - mhi * mhi;
        float rshi = rsqrtf(vhi + 1e-5f);
        #pragma unroll
        for (int j = 0; j < 4; ++j) {
            int col = wx * 32 + j * 8 + tig * 2;
            float2 o0, o1;
            o0.x = (acc3[i][j][0] - mlo) * rslo;
            o0.y = (acc3[i][j][1] - mlo) * rslo;
            o1.x = (acc3[i][j][2] - mhi) * rshi;
            o1.y = (acc3[i][j][3] - mhi) * rshi;
            *(float2*)(outp + (m0 + rlo) * FF + col) = o0;
            *(float2*)(outp + (m0 + rhi) * FF + col) = o1;
        }
    }
}

// =====================================================================
extern "C" void kernel_launch(void* const* d_in, const int* in_sizes, int n_in,
                              void* d_out, int out_size)
{
    const float* xl  = (const float*)d_in[0];
    const float* xh  = (const float*)d_in[1];
    const float* te  = (const float*)d_in[2];
    const float* Wq  = (const float*)d_in[3];
    const float* bq  = (const float*)d_in[4];
    const float* Wkh = (const float*)d_in[5];
    const float* bkh = (const float*)d_in[6];
    const float* Wvh = (const float*)d_in[7];
    const float* bvh = (const float*)d_in[8];
    const float* Wo  = (const float*)d_in[9];
    const float* bo  = (const float*)d_in[10];
    const float* Wf1 = (const float*)d_in[11];
    const float* bf1 = (const float*)d_in[12];
    const float* Wf2 = (const float*)d_in[13];
    const float* bf2 = (const float*)d_in[14];
    float* outp = (float*)d_out;

    const int smFused = 5 * 128 * HP * 2 + 2 * 1024;          // 176128
    const int smTail  = 3 * 128 * HP * 2 + 4096;              // 108544

    cudaFuncSetAttribute(fused_attn_kernel, cudaFuncAttributeMaxDynamicSharedMemorySize, smFused);
    cudaFuncSetAttribute(tail_kernel,       cudaFuncAttributeMaxDynamicSharedMemorySize, smTail);

    conv_kernel<<<16, 256>>>(Wq, Wkh, Wvh, Wo, Wf1, Wf2);
    fused_attn_kernel<<<BB * NN, 512, smFused>>>(xl, xh, te, bq, bkh, bvh);
    tail_kernel<<<MTOT / 128, 256, smTail>>>(outp, xl, te, bo, bf1, bf2);
}

// round 11
// speedup vs baseline: 1.3170x; 1.1541x over previous
#include <cuda_runtime.h>
#include <cuda_fp16.h>
#include <math.h>

constexpr int BB = 8;
constexpr int TT = 128;
constexpr int NN = 256;
constexpr int FF = 128;
constexpr int MTOT = BB * TT * NN;   // 262144
constexpr int HP = 136;              // smem half pitch (padded)

// -------- scratch (device globals) --------
__device__ __half g_attn[MTOT * FF];
// transposed [n][k] fp16 weights for the qkv GEMMs (B-fragments via LDG)
__device__ __align__(16) __half g_wqT [FF * FF];
__device__ __align__(16) __half g_wkhT[FF * FF];
__device__ __align__(16) __half g_wvhT[FF * FF];
// normal [k][n] fp16 weights for the tail kernel (smem + ldsm path)
__device__ __align__(16) __half g_wo16 [FF * FF];
__device__ __align__(16) __half g_wf116[FF * FF];
__device__ __align__(16) __half g_wf216[FF * FF];

// ------------------- asm helpers -------------------
__device__ __forceinline__ unsigned sptr(const void* ptr) {
    return (unsigned)__cvta_generic_to_shared(ptr);
}
__device__ __forceinline__ void ldsm4(unsigned& r0, unsigned& r1, unsigned& r2, unsigned& r3, unsigned addr) {
    asm volatile("ldmatrix.sync.aligned.m8n8.x4.shared.b16 {%0,%1,%2,%3},[%4];"
                 : "=r"(r0), "=r"(r1), "=r"(r2), "=r"(r3) : "r"(addr));
}
__device__ __forceinline__ void ldsm4t(unsigned& r0, unsigned& r1, unsigned& r2, unsigned& r3, unsigned addr) {
    asm volatile("ldmatrix.sync.aligned.m8n8.x4.trans.shared.b16 {%0,%1,%2,%3},[%4];"
                 : "=r"(r0), "=r"(r1), "=r"(r2), "=r"(r3) : "r"(addr));
}
__device__ __forceinline__ void mma16816(float* cc, const unsigned* aa, const unsigned* bb) {
    asm volatile("mma.sync.aligned.m16n8k16.row.col.f32.f16.f16.f32 "
                 "{%0,%1,%2,%3},{%4,%5,%6,%7},{%8,%9},{%0,%1,%2,%3};"
                 : "+f"(cc[0]), "+f"(cc[1]), "+f"(cc[2]), "+f"(cc[3])
                 : "r"(aa[0]), "r"(aa[1]), "r"(aa[2]), "r"(aa[3]), "r"(bb[0]), "r"(bb[1]));
}
__device__ __forceinline__ unsigned pack2(float a, float b) {
    __half2 h = __floats2half2_rn(a, b);
    return *reinterpret_cast<unsigned*>(&h);
}
__device__ __forceinline__ void cpa16(void* dst, const void* src) {
    asm volatile("cp.async.cg.shared.global [%0], [%1], 16;"
                 :: "r"(sptr(dst)), "l"(src));
}
__device__ __forceinline__ void cpcommit() {
    asm volatile("cp.async.commit_group;");
}
template<int N> __device__ __forceinline__ void cpwait() {
    asm volatile("cp.async.wait_group %0;" :: "n"(N));
}

// ---------- 256-thread tile GEMM, B from smem ldsm (tail kernel) ----------
__device__ __forceinline__ void mma_tile(const __half* Amat, const __half* Bmat, float acc[4][4][4]) {
    const int lane = threadIdx.x & 31;
    const int warp = threadIdx.x >> 5;
    const int wy = warp >> 2;
    const int wx = warp & 3;
    const int r16 = lane & 15;
    const int hi8 = (lane >> 4) * 8;
    #pragma unroll
    for (int k0 = 0; k0 < 128; k0 += 16) {
        unsigned afrag[4][4];
        #pragma unroll
        for (int i = 0; i < 4; ++i) {
            unsigned addr = sptr(Amat + (wy * 64 + i * 16 + r16) * HP + k0 + hi8);
            ldsm4(afrag[i][0], afrag[i][1], afrag[i][2], afrag[i][3], addr);
        }
        unsigned bfrag[4][2];
        #pragma unroll
        for (int jj = 0; jj < 2; ++jj) {
            unsigned addr = sptr(Bmat + (k0 + r16) * HP + wx * 32 + jj * 16 + hi8);
            unsigned t0, t1, t2, t3;
            ldsm4t(t0, t1, t2, t3, addr);
            bfrag[jj * 2 + 0][0] = t0; bfrag[jj * 2 + 0][1] = t1;
            bfrag[jj * 2 + 1][0] = t2; bfrag[jj * 2 + 1][1] = t3;
        }
        #pragma unroll
        for (int i = 0; i < 4; ++i)
            #pragma unroll
            for (int j = 0; j < 4; ++j)
                mma16816(acc[i][j], afrag[i], bfrag[j]);
    }
}

// ---------- 256-thread tile GEMM, B-fragments via LDG from transposed weight ----------
// Wt layout: [n][k], n rows of 128 contiguous halves.
// b0 = {Wt[n][k0+2tig], Wt[n][k0+2tig+1]}, b1 = same +8, n = wx*32 + j*8 + gid.
__device__ __forceinline__ void mma_tile_ldg(const __half* Amat, const __half* __restrict__ Wt,
                                             float acc[4][4][4]) {
    const int lane = threadIdx.x & 31;
    const int warp = threadIdx.x >> 5;
    const int wy = warp >> 2;
    const int wx = warp & 3;
    const int r16 = lane & 15;
    const int hi8 = (lane >> 4) * 8;
    const int gid = lane >> 2;
    const int tig = lane & 3;
    const __half* bbase = Wt + (wx * 32 + gid) * 128 + tig * 2;
    #pragma unroll
    for (int k0 = 0; k0 < 128; k0 += 16) {
        unsigned afrag[4][4];
        #pragma unroll
        for (int i = 0; i < 4; ++i) {
            unsigned addr = sptr(Amat + (wy * 64 + i * 16 + r16) * HP + k0 + hi8);
            ldsm4(afrag[i][0], afrag[i][1], afrag[i][2], afrag[i][3], addr);
        }
        unsigned bfrag[4][2];
        #pragma unroll
        for (int j = 0; j < 4; ++j) {
            const __half* bp = bbase + j * 8 * 128 + k0;
            bfrag[j][0] = *(const unsigned*)(bp);
            bfrag[j][1] = *(const unsigned*)(bp + 8);
        }
        #pragma unroll
        for (int i = 0; i < 4; ++i)
            #pragma unroll
            for (int j = 0; j < 4; ++j)
                mma16816(acc[i][j], afrag[i], bfrag[j]);
    }
}

// writeback accumulators (+bias, optional relu) into an f16 smem tile [128][HP]
__device__ __forceinline__ void store_tile(__half* dst, float acc[4][4][4],
                                           const float* __restrict__ bias, bool doRelu) {
    const int lane = threadIdx.x & 31;
    const int warp = threadIdx.x >> 5;
    const int wy = warp >> 2;
    const int wx = warp & 3;
    const int gid = lane >> 2;
    const int tig = lane & 3;
    #pragma unroll
    for (int i = 0; i < 4; ++i) {
        int row = wy * 64 + i * 16 + gid;
        #pragma unroll
        for (int j = 0; j < 4; ++j) {
            int col = wx * 32 + j * 8 + tig * 2;
            float2 bv = *(const float2*)(bias + col);
            float o0 = acc[i][j][0] + bv.x;
            float o1 = acc[i][j][1] + bv.y;
            float o2 = acc[i][j][2] + bv.x;
            float o3 = acc[i][j][3] + bv.y;
            if (doRelu) {
                o0 = fmaxf(o0, 0.f); o1 = fmaxf(o1, 0.f);
                o2 = fmaxf(o2, 0.f); o3 = fmaxf(o3, 0.f);
            }
            *(__half2*)(dst + row * HP + col)       = __floats2half2_rn(o0, o1);
            *(__half2*)(dst + (row + 8) * HP + col) = __floats2half2_rn(o2, o3);
        }
    }
}

// =====================================================================
// Kernel 0: fp32 -> fp16 weight conversion. qkv weights transposed [n][k].
// =====================================================================
__global__ void conv_kernel(const float* __restrict__ Wq, const float* __restrict__ Wkh,
                            const float* __restrict__ Wvh, const float* __restrict__ Wo,
                            const float* __restrict__ Wf1, const float* __restrict__ Wf2)
{
    int i = blockIdx.x * 256 + threadIdx.x;   // [0, 4096): one float4 per matrix
    int krow = i >> 5;                        // k row in the fp32 [k][n] layout
    int n0 = (i & 31) * 4;                    // starting n column
    float4 a;

    a = ((const float4*)Wq)[i];
    g_wqT[(n0 + 0) * 128 + krow] = __float2half(a.x);
    g_wqT[(n0 + 1) * 128 + krow] = __float2half(a.y);
    g_wqT[(n0 + 2) * 128 + krow] = __float2half(a.z);
    g_wqT[(n0 + 3) * 128 + krow] = __float2half(a.w);

    a = ((const float4*)Wkh)[i];
    g_wkhT[(n0 + 0) * 128 + krow] = __float2half(a.x);
    g_wkhT[(n0 + 1) * 128 + krow] = __float2half(a.y);
    g_wkhT[(n0 + 2) * 128 + krow] = __float2half(a.z);
    g_wkhT[(n0 + 3) * 128 + krow] = __float2half(a.w);

    a = ((const float4*)Wvh)[i];
    g_wvhT[(n0 + 0) * 128 + krow] = __float2half(a.x);
    g_wvhT[(n0 + 1) * 128 + krow] = __float2half(a.y);
    g_wvhT[(n0 + 2) * 128 + krow] = __float2half(a.z);
    g_wvhT[(n0 + 3) * 128 + krow] = __float2half(a.w);

    a = ((const float4*)Wo)[i];
    ((__half2*)g_wo16)[2 * i]     = __floats2half2_rn(a.x, a.y);
    ((__half2*)g_wo16)[2 * i + 1] = __floats2half2_rn(a.z, a.w);
    a = ((const float4*)Wf1)[i];
    ((__half2*)g_wf116)[2 * i]     = __floats2half2_rn(a.x, a.y);
    ((__half2*)g_wf116)[2 * i + 1] = __floats2half2_rn(a.z, a.w);
    a = ((const float4*)Wf2)[i];
    ((__half2*)g_wf216)[2 * i]     = __floats2half2_rn(a.x, a.y);
    ((__half2*)g_wf216)[2 * i + 1] = __floats2half2_rn(a.z, a.w);
}

// =====================================================================
// Attention warp body (R7 register version): warp w owns rows [16w,16w+16),
// computes s-tile-pairs jp <= w. No extra smem, writes g_attn directly.
// =====================================================================
template<int NP>
__device__ __forceinline__ void attn_warp(const __half* Qs, const __half* Ks, const __half* Vs,
                                          int base, int w, int lane)
{
    const int r16 = lane & 15;
    const int hi8 = (lane >> 4) * 8;
    const int gid = lane >> 2;
    const int tig = lane & 3;

    unsigned aq[8][4];
    #pragma unroll
    for (int k = 0; k < 8; ++k) {
        unsigned addr = sptr(Qs + (16 * w + r16) * HP + k * 16 + hi8);
        ldsm4(aq[k][0], aq[k][1], aq[k][2], aq[k][3], addr);
    }

    float c[2 * NP][4];
    #pragma unroll
    for (int js = 0; js < 2 * NP; ++js) {
        c[js][0] = 0.f; c[js][1] = 0.f; c[js][2] = 0.f; c[js][3] = 0.f;
    }
    #pragma unroll
    for (int jp = 0; jp < NP; ++jp) {
        #pragma unroll
        for (int k = 0; k < 8; ++k) {
            unsigned t0, t1, t2, t3;
            unsigned addr = sptr(Ks + (16 * jp + r16) * HP + k * 16 + hi8);
            ldsm4(t0, t1, t2, t3, addr);
            unsigned bE[2] = { t0, t2 };
            unsigned bO[2] = { t1, t3 };
            mma16816(c[2 * jp],     aq[k], bE);
            mma16816(c[2 * jp + 1], aq[k], bO);
        }
    }

    const float scale = 0.08838834764831845f;   // 1/sqrt(128)
    const int tlo = 16 * w + gid;
    const int thi = tlo + 8;
    float mlo = -1e30f, mhi = -1e30f;
    #pragma unroll
    for (int js = 0; js < 2 * NP; ++js) {
        int s0 = 8 * js + 2 * tig;
        int s1 = s0 + 1;
        c[js][0] *= scale; c[js][1] *= scale;
        c[js][2] *= scale; c[js][3] *= scale;
        if (js >= 2 * NP - 2) {          // diagonal block: causal mask
            if (s0 > tlo) c[js][0] = -1e30f;
            if (s1 > tlo) c[js][1] = -1e30f;
            if (s0 > thi) c[js][2] = -1e30f;
            if (s1 > thi) c[js][3] = -1e30f;
        }
        mlo = fmaxf(mlo, fmaxf(c[js][0], c[js][1]));
        mhi = fmaxf(mhi, fmaxf(c[js][2], c[js][3]));
    }
    #pragma unroll
    for (int o = 1; o <= 2; o <<= 1) {
        mlo = fmaxf(mlo, __shfl_xor_sync(0xffffffffu, mlo, o));
        mhi = fmaxf(mhi, __shfl_xor_sync(0xffffffffu, mhi, o));
    }
    float slo = 0.f, shi = 0.f;
    #pragma unroll
    for (int js = 0; js < 2 * NP; ++js) {
        c[js][0] = __expf(c[js][0] - mlo);
        c[js][1] = __expf(c[js][1] - mlo);
        c[js][2] = __expf(c[js][2] - mhi);
        c[js][3] = __expf(c[js][3] - mhi);
        slo += c[js][0] + c[js][1];
        shi += c[js][2] + c[js][3];
    }
    #pragma unroll
    for (int o = 1; o <= 2; o <<= 1) {
        slo += __shfl_xor_sync(0xffffffffu, slo, o);
        shi += __shfl_xor_sync(0xffffffffu, shi, o);
    }
    const float invlo = 1.f / slo;
    const float invhi = 1.f / shi;

    float ov[16][4];
    #pragma unroll
    for (int jt = 0; jt < 16; ++jt) {
        ov[jt][0] = 0.f; ov[jt][1] = 0.f; ov[jt][2] = 0.f; ov[jt][3] = 0.f;
    }
    #pragma unroll
    for (int ks = 0; ks < NP; ++ks) {
        unsigned ap[4];
        ap[0] = pack2(c[2 * ks][0],     c[2 * ks][1]);
        ap[1] = pack2(c[2 * ks][2],     c[2 * ks][3]);
        ap[2] = pack2(c[2 * ks + 1][0], c[2 * ks + 1][1]);
        ap[3] = pack2(c[2 * ks + 1][2], c[2 * ks + 1][3]);
        #pragma unroll
        for (int jf = 0; jf < 8; ++jf) {
            unsigned t0, t1, t2, t3;
            unsigned addr = sptr(Vs + (16 * ks + r16) * HP + jf * 16 + hi8);
            ldsm4t(t0, t1, t2, t3, addr);
            unsigned b0[2] = { t0, t1 };
            unsigned b1[2] = { t2, t3 };
            mma16816(ov[2 * jf],     ap, b0);
            mma16816(ov[2 * jf + 1], ap, b1);
        }
    }

    __half* olo = g_attn + (base + tlo * NN) * FF;
    __half* ohi = g_attn + (base + thi * NN) * FF;
    #pragma unroll
    for (int jt = 0; jt < 16; ++jt) {
        int col = jt * 8 + tig * 2;
        *(__half2*)(olo + col) = __floats2half2_rn(ov[jt][0] * invlo, ov[jt][1] * invlo);
        *(__half2*)(ohi + col) = __floats2half2_rn(ov[jt][2] * invhi, ov[jt][3] * invhi);
    }
}

// =====================================================================
// Kernel 1 (fused qkv + attention), 256 threads, 2 CTAs/SM.
// 3 smem buffers; weight B-fragments via LDG from transposed globals.
//   X1 = xh+te -> K;  X2 = xl+te -> Q;  C = V.
// =====================================================================
__global__ __launch_bounds__(256, 2) void fused_attn_kernel(
    const float* __restrict__ xl, const float* __restrict__ xh,
    const float* __restrict__ te,
    const float* __restrict__ bq, const float* __restrict__ bkh,
    const float* __restrict__ bvh)
{
    extern __shared__ char smraw[];
    __half* X1 = (__half*)smraw;          // xh+te -> later K
    __half* X2 = X1 + 128 * HP;           // xl+te -> later Q
    __half* C  = X2 + 128 * HP;           // V

    const int head = blockIdx.x;
    const int bidx = head >> 8;
    const int nidx = head & 255;
    const int base = bidx * TT * NN + nidx;   // row(t)=base+t*NN

    const int tid = threadIdx.x;
    const int w = tid >> 5;
    const int lane = tid & 31;

    const float4* xl4 = (const float4*)xl;
    const float4* xh4 = (const float4*)xh;
    const float4* te4 = (const float4*)te;

    // ---- stage X1 = xh+te, X2 = xl+te ----
    #pragma unroll
    for (int v = tid; v < 4096; v += 256) {
        int row = v >> 5;
        int c4 = v & 31;
        float4 tval = te4[(bidx * TT + row) * 32 + c4];
        float4 ah = xh4[(base + row * NN) * 32 + c4];
        __half2* dh = (__half2*)(X1 + row * HP + c4 * 4);
        dh[0] = __floats2half2_rn(ah.x + tval.x, ah.y + tval.y);
        dh[1] = __floats2half2_rn(ah.z + tval.z, ah.w + tval.w);
        float4 al = xl4[(base + row * NN) * 32 + c4];
        __half2* dl = (__half2*)(X2 + row * HP + c4 * 4);
        dl[0] = __floats2half2_rn(al.x + tval.x, al.y + tval.y);
        dl[1] = __floats2half2_rn(al.z + tval.z, al.w + tval.w);
    }
    __syncthreads();

    // ---- V GEMM -> C (C free, no sync needed for the store) ----
    {
        float accV[4][4][4] = {};
        mma_tile_ldg(X1, g_wvhT, accV);
        store_tile(C, accV, bvh, true);
    }
    // ---- K GEMM ----
    {
        float accK[4][4][4] = {};
        mma_tile_ldg(X1, g_wkhT, accK);
        __syncthreads();                 // all X1 reads (V & K GEMMs) done
        store_tile(X1, accK, bkh, true); // K -> X1
    }
    // ---- Q GEMM ----
    {
        float accQ[4][4][4] = {};
        mma_tile_ldg(X2, g_wqT, accQ);
        __syncthreads();                 // all X2 reads done; K store visible
        store_tile(X2, accQ, bq, false); // Q -> X2
    }
    __syncthreads();                     // Q/K/V visible

    // ---- causal attention: Q=X2, K=X1, V=C ----
    switch (w) {
        case 0: attn_warp<1>(X2, X1, C, base, 0, lane); break;
        case 1: attn_warp<2>(X2, X1, C, base, 1, lane); break;
        case 2: attn_warp<3>(X2, X1, C, base, 2, lane); break;
        case 3: attn_warp<4>(X2, X1, C, base, 3, lane); break;
        case 4: attn_warp<5>(X2, X1, C, base, 4, lane); break;
        case 5: attn_warp<6>(X2, X1, C, base, 5, lane); break;
        case 6: attn_warp<7>(X2, X1, C, base, 6, lane); break;
        default: attn_warp<8>(X2, X1, C, base, 7, lane); break;
    }
}

// =====================================================================
// Kernel 2 (fused proj+ffn), 256 threads, 2 CTAs/SM (unchanged from R10).
// =====================================================================
__global__ __launch_bounds__(256, 2) void tail_kernel(
    float* __restrict__ outp,
    const float* __restrict__ xl, const float* __restrict__ te,
    const float* __restrict__ bo, const float* __restrict__ bf1,
    const float* __restrict__ bf2)
{
    extern __shared__ char smraw[];
    __half* A1 = (__half*)smraw;          // attn -> ln1 (f16)
    __half* A2 = A1 + 128 * HP;           // Wf1 -> h
    __half* Wb = A2 + 128 * HP;           // Wo -> Wf2
    float* red1 = (float*)(Wb + 128 * HP);
    float* red2 = red1 + 512;

    const int m0 = blockIdx.x * 128;
    const int tid = threadIdx.x;
    const float* teRow = te + (m0 / NN) * FF;

    #pragma unroll
    for (int v = tid; v < 2048; v += 256) {
        int row = v >> 4;
        int q16 = v & 15;
        cpa16(A2 + row * HP + q16 * 8, ((const uint4*)g_wf116) + row * 16 + q16);
    }
    cpcommit();

    #pragma unroll
    for (int v = tid; v < 2048; v += 256) {
        int row = v >> 4;
        int q16 = v & 15;
        ((uint4*)(A1 + row * HP))[q16] = ((const uint4*)(g_attn + (m0 + row) * FF))[q16];
        ((uint4*)(Wb + row * HP))[q16] = ((const uint4*)g_wo16)[row * 16 + q16];
    }
    __syncthreads();

    const int lane = tid & 31;
    const int warp = tid >> 5;
    const int wy = warp >> 2;
    const int wx = warp & 3;
    const int gid = lane >> 2;
    const int tig = lane & 3;

    float acc[4][4][4] = {};
    mma_tile(A1, Wb, acc);
    __syncthreads();

    #pragma unroll
    for (int v = tid; v < 2048; v += 256) {
        int row = v >> 4;
        int q16 = v & 15;
        cpa16(Wb + row * HP + q16 * 8, ((const uint4*)g_wf216) + row * 16 + q16);
    }
    cpcommit();

    #pragma unroll
    for (int i = 0; i < 4; ++i) {
        int rlo = wy * 64 + i * 16 + gid;
        int rhi = rlo + 8;
        float s1lo = 0.f, s2lo = 0.f, s1hi = 0.f, s2hi = 0.f;
        #pragma unroll
        for (int j = 0; j < 4; ++j) {
            int col = wx * 32 + j * 8 + tig * 2;
            float2 bv = *(const float2*)(bo + col);
            float2 x0 = *(const float2*)(xl + (m0 + rlo) * FF + col);
            float2 x1 = *(const float2*)(xl + (m0 + rhi) * FF + col);
            float2 t0 = *(const float2*)(teRow + col);
            float v0 = acc[i][j][0] + bv.x + x0.x + t0.x;
            float v1 = acc[i][j][1] + bv.y + x0.y + t0.y;
            float v2 = acc[i][j][2] + bv.x + x1.x + t0.x;
            float v3 = acc[i][j][3] + bv.y + x1.y + t0.y;
            acc[i][j][0] = v0; acc[i][j][1] = v1;
            acc[i][j][2] = v2; acc[i][j][3] = v3;
            s1lo += v0 + v1; s2lo += v0 * v0 + v1 * v1;
            s1hi += v2 + v3; s2hi += v2 * v2 + v3 * v3;
        }
        #pragma unroll
        for (int o = 1; o <= 2; o <<= 1) {
            s1lo += __shfl_xor_sync(0xffffffffu, s1lo, o);
            s2lo += __shfl_xor_sync(0xffffffffu, s2lo, o);
            s1hi += __shfl_xor_sync(0xffffffffu, s1hi, o);
            s2hi += __shfl_xor_sync(0xffffffffu, s2hi, o);
        }
        if (tig == 0) {
            red1[rlo * 4 + wx] = s1lo; red2[rlo * 4 + wx] = s2lo;
            red1[rhi * 4 + wx] = s1hi; red2[rhi * 4 + wx] = s2hi;
        }
    }
    __syncthreads();

    #pragma unroll
    for (int i = 0; i < 4; ++i) {
        int rlo = wy * 64 + i * 16 + gid;
        int rhi = rlo + 8;
        float mlo = (red1[rlo * 4] + red1[rlo * 4 + 1] + red1[rlo * 4 + 2] + red1[rlo * 4 + 3]) * 0.0078125f;
        float vlo = (red2[rlo * 4] + red2[rlo * 4 + 1] + red2[rlo * 4 + 2] + red2[rlo * 4 + 3]) * 0.0078125f - mlo * mlo;
        float rslo = rsqrtf(vlo + 1e-5f);
        float mhi = (red1[rhi * 4] + red1[rhi * 4 + 1] + red1[rhi * 4 + 2] + red1[rhi * 4 + 3]) * 0.0078125f;
        float vhi = (red2[rhi * 4] + red2[rhi * 4 + 1] + red2[rhi * 4 + 2] + red2[rhi * 4 + 3]) * 0.0078125f - mhi * mhi;
        float rshi = rsqrtf(vhi + 1e-5f);
        #pragma unroll
        for (int j = 0; j < 4; ++j) {
            int col = wx * 32 + j * 8 + tig * 2;
            *(__half2*)(A1 + rlo * HP + col) =
                __floats2half2_rn((acc[i][j][0] - mlo) * rslo, (acc[i][j][1] - mlo) * rslo);
            *(__half2*)(A1 + rhi * HP + col) =
                __floats2half2_rn((acc[i][j][2] - mhi) * rshi, (acc[i][j][3] - mhi) * rshi);
        }
    }
    cpwait<1>();       // Wf1 complete
    __syncthreads();

    float acc2[4][4][4] = {};
    mma_tile(A1, A2, acc2);
    __syncthreads();
    store_tile(A2, acc2, bf1, true);
    cpwait<0>();       // Wf2 complete
    __syncthreads();

    float acc3[4][4][4] = {};
    mma_tile(A2, Wb, acc3);

    #pragma unroll
    for (int i = 0; i < 4; ++i) {
        int rlo = wy * 64 + i * 16 + gid;
        int rhi = rlo + 8;
        float s1lo = 0.f, s2lo = 0.f, s1hi = 0.f, s2hi = 0.f;
        #pragma unroll
        for (int j = 0; j < 4; ++j) {
            int col = wx * 32 + j * 8 + tig * 2;
            float2 bv = *(const float2*)(bf2 + col);
            float2 l0 = __half22float2(*(const __half2*)(A1 + rlo * HP + col));
            float2 l1 = __half22float2(*(const __half2*)(A1 + rhi * HP + col));
            float v0 = acc3[i][j][0] + bv.x + l0.x;
            float v1 = acc3[i][j][1] + bv.y + l0.y;
            float v2 = acc3[i][j][2] + bv.x + l1.x;
            float v3 = acc3[i][j][3] + bv.y + l1.y;
            acc3[i][j][0] = v0; acc3[i][j][1] = v1;
            acc3[i][j][2] = v2; acc3[i][j][3] = v3;
            s1lo += v0 + v1; s2lo += v0 * v0 + v1 * v1;
            s1hi += v2 + v3; s2hi += v2 * v2 + v3 * v3;
        }
        #pragma unroll
        for (int o = 1; o <= 2; o <<= 1) {
            s1lo += __shfl_xor_sync(0xffffffffu, s1lo, o);
            s2lo += __shfl_xor_sync(0xffffffffu, s2lo, o);
            s1hi += __shfl_xor_sync(0xffffffffu, s1hi, o);
            s2hi += __shfl_xor_sync(0xffffffffu, s2hi, o);
        }
        if (tig == 0) {
            red1[rlo * 4 + wx] = s1lo; red2[rlo * 4 + wx] = s2lo;
            red1[rhi * 4 + wx] = s1hi; red2[rhi * 4 + wx] = s2hi;
        }
    }
    __syncthreads();

    #pragma unroll
    for (int i = 0; i < 4; ++i) {
        int rlo = wy * 64 + i * 16 + gid;
        int rhi = rlo + 8;
        float mlo = (red1[rlo * 4] + red1[rlo * 4 + 1] + red1[rlo * 4 + 2] + red1[rlo * 4 + 3]) * 0.0078125f;
        float vlo = (red2[rlo * 4] + red2[rlo * 4 + 1] + red2[rlo * 4 + 2] + red2[rlo * 4 + 3]) * 0.0078125f - mlo * mlo;
        float rslo = rsqrtf(vlo + 1e-5f);
        float mhi = (red1[rhi * 4] + red1[rhi * 4 + 1] + red1[rhi * 4 + 2] + red1[rhi * 4 + 3]) * 0.0078125f;
        float vhi = (red2[rhi * 4] + red2[rhi * 4 + 1] + red2[rhi * 4 + 2] + red2[rhi * 4 + 3]) * 0.0078125f - mhi * mhi;
        float rshi = rsqrtf(vhi + 1e-5f);
        #pragma unroll
        for (int j = 0; j < 4; ++j) {
            int col = wx * 32 + j * 8 + tig * 2;
            float2 o0, o1;
            o0.x = (acc3[i][j][0] - mlo) * rslo;
            o0.y = (acc3[i][j][1] - mlo) * rslo;
            o1.x = (acc3[i][j][2] - mhi) * rshi;
            o1.y = (acc3[i][j][3] - mhi) * rshi;
            *(float2*)(outp + (m0 + rlo) * FF + col) = o0;
            *(float2*)(outp + (m0 + rhi) * FF + col) = o1;
        }
    }
}

// =====================================================================
extern "C" void kernel_launch(void* const* d_in, const int* in_sizes, int n_in,
                              void* d_out, int out_size)
{
    const float* xl  = (const float*)d_in[0];
    const float* xh  = (const float*)d_in[1];
    const float* te  = (const float*)d_in[2];
    const float* Wq  = (const float*)d_in[3];
    const float* bq  = (const float*)d_in[4];
    const float* Wkh = (const float*)d_in[5];
    const float* bkh = (const float*)d_in[6];
    const float* Wvh = (const float*)d_in[7];
    const float* bvh = (const float*)d_in[8];
    const float* Wo  = (const float*)d_in[9];
    const float* bo  = (const float*)d_in[10];
    const float* Wf1 = (const float*)d_in[11];
    const float* bf1 = (const float*)d_in[12];
    const float* Wf2 = (const float*)d_in[13];
    const float* bf2 = (const float*)d_in[14];
    float* outp = (float*)d_out;

    const int smFused = 3 * 128 * HP * 2;                     // 104448
    const int smTail  = 3 * 128 * HP * 2 + 4096;              // 108544

    cudaFuncSetAttribute(fused_attn_kernel, cudaFuncAttributeMaxDynamicSharedMemorySize, smFused);
    cudaFuncSetAttribute(tail_kernel,       cudaFuncAttributeMaxDynamicSharedMemorySize, smTail);

    conv_kernel<<<16, 256>>>(Wq, Wkh, Wvh, Wo, Wf1, Wf2);
    fused_attn_kernel<<<BB * NN, 256, smFused>>>(xl, xh, te, bq, bkh, bvh);
    tail_kernel<<<MTOT / 128, 256, smTail>>>(outp, xl, te, bo, bf1, bf2);
}